// round 10
// baseline (speedup 1.0000x reference)
#include <cuda_runtime.h>
#include <cuda_bf16.h>
#include <cstdint>

// ---------------------------------------------------------------------------
// Problem constants
// ---------------------------------------------------------------------------
#define BATCH   4
#define SEQ     4096
#define TOKENS  (BATCH * SEQ)        // 16384
#define DMODEL  1024
#define DINNER  1024
#define NHEADS  16
#define HDIM    64
#define DSTATE  16
#define DTRANK  16
#define CHUNK   64
#define NCHUNK  (SEQ / CHUNK)        // 64
#define PROJ    2576
#define PROJPAD 2688                 // 21 * 128

#define OFF_XP   0
#define OFF_Z    1024
#define OFF_B    2048
#define OFF_C    2304
#define OFF_DT   2560

// Packed-operand block offsets (bytes). A-pack: 256-row tiles; B-pack: 128-row.
// Both GEMMs have K=1024 -> exactly 16 chunks of 64 columns.
#define APK_BLK(mt, ch) ((((size_t)(mt) * 16) + (size_t)(ch)) * 32768)
#define BPK_BLK(nt, ch) ((((size_t)(nt) * 16) + (size_t)(ch)) * 16384)
#define SW128(o) ((o) ^ (((o) >> 3) & 0x70))

// tcgen05 is an arch-SPECIFIC feature: only emit it in the sm_103a/f passes.
#if defined(__CUDA_ARCH_FEAT_SM103_ALL) || \
    (defined(__CUDA_ARCH_FAMILY_SPECIFIC__) && __CUDA_ARCH_FAMILY_SPECIFIC__ >= 1000) || \
    (defined(__CUDA_ARCH_SPECIFIC__) && __CUDA_ARCH_SPECIFIC__ >= 1000)
#define HAS_TCGEN05 1
#else
#define HAS_TCGEN05 0
#endif

// ---------------------------------------------------------------------------
// PTX helpers (guarded)
// ---------------------------------------------------------------------------
#if HAS_TCGEN05
__device__ __forceinline__ uint32_t smem_to_u32(const void* p) {
    uint32_t a;
    asm("{ .reg .u64 t; cvta.to.shared.u64 t, %1; cvt.u32.u64 %0, t; }" : "=r"(a) : "l"(p));
    return a;
}
__device__ __forceinline__ uint32_t elect_one_pred() {
    uint32_t pred;
    asm volatile("{\n\t.reg .pred p;\n\telect.sync _|p, 0xFFFFFFFF;\n\tselp.b32 %0, 1, 0, p;\n\t}" : "=r"(pred));
    return pred;
}
#define TCGEN05_ALLOC(smem_result_addr, nCols) \
    asm volatile("tcgen05.alloc.cta_group::1.sync.aligned.shared::cta.b32 [%0], %1;" \
        :: "r"((uint32_t)(smem_result_addr)), "r"((uint32_t)(nCols)) : "memory")
#define TCGEN05_DEALLOC(tmem_addr, nCols) \
    asm volatile("tcgen05.dealloc.cta_group::1.sync.aligned.b32 %0, %1;" :: "r"(tmem_addr), "r"((uint32_t)(nCols)))
#define TCGEN05_RELINQUISH() \
    asm volatile("tcgen05.relinquish_alloc_permit.cta_group::1.sync.aligned;")
#define TCGEN05_COMMIT(mbar) \
    asm volatile("tcgen05.commit.cta_group::1.mbarrier::arrive::one.shared::cluster.b64 [%0];" \
        :: "r"((uint32_t)(mbar)) : "memory")
#define TCGEN05_FENCE_AFTER()  asm volatile("tcgen05.fence::after_thread_sync;" ::: "memory")
#define TCGEN05_FENCE_BEFORE() asm volatile("tcgen05.fence::before_thread_sync;" ::: "memory")
#define TCGEN05_WAIT_LD()      asm volatile("tcgen05.wait::ld.sync.aligned;" ::: "memory")
#define MBARRIER_INIT(mbar, count) \
    asm volatile("mbarrier.init.shared.b64 [%0], %1;" :: "r"((uint32_t)(mbar)), "r"((uint32_t)(count)) : "memory")
#define FENCE_PROXY_ASYNC() asm volatile("fence.proxy.async.shared::cta;" ::: "memory")
#define CP_ASYNC16(dst, src) \
    asm volatile("cp.async.cg.shared.global [%0], [%1], 16;" \
        :: "r"((uint32_t)(dst)), "l"(src) : "memory")
#define CP_ASYNC_COMMIT() asm volatile("cp.async.commit_group;" ::: "memory")
#define CP_ASYNC_WAIT0()  asm volatile("cp.async.wait_group 0;" ::: "memory")
#define MBARRIER_WAIT_PARITY(mbar, parity) do { \
    uint32_t _m = (uint32_t)(mbar); uint32_t _p = (uint32_t)(parity); uint32_t _d; \
    asm volatile("{\n\t.reg .pred p;\n\t" \
        "mbarrier.try_wait.parity.acquire.cta.shared::cta.b64 p, [%1], %2;\n\t" \
        "selp.b32 %0, 1, 0, p;\n\t}" : "=r"(_d) : "r"(_m), "r"(_p) : "memory"); \
    if (!_d) { \
        asm volatile("{\n\t.reg .pred P1;\n\t" \
            "WL_%=:\n\t" \
            "mbarrier.try_wait.parity.acquire.cta.shared::cta.b64 P1, [%0], %1, 0x989680;\n\t" \
            "@P1 bra.uni WD_%=;\n\t" \
            "bra.uni WL_%=;\n\t" \
            "WD_%=:\n\t}" :: "r"(_m), "r"(_p) : "memory"); \
    } } while (0)
#define TCGEN05_LD_32X32B_X32(r, tmem_addr) \
    asm volatile("tcgen05.ld.sync.aligned.32x32b.x32.b32 " \
        "{%0, %1, %2, %3, %4, %5, %6, %7, %8, %9, %10, %11, %12, %13, %14, %15, " \
        " %16, %17, %18, %19, %20, %21, %22, %23, %24, %25, %26, %27, %28, %29, %30, %31}, [%32];" \
        : "=r"((r)[0]),  "=r"((r)[1]),  "=r"((r)[2]),  "=r"((r)[3]), \
          "=r"((r)[4]),  "=r"((r)[5]),  "=r"((r)[6]),  "=r"((r)[7]), \
          "=r"((r)[8]),  "=r"((r)[9]),  "=r"((r)[10]), "=r"((r)[11]), \
          "=r"((r)[12]), "=r"((r)[13]), "=r"((r)[14]), "=r"((r)[15]), \
          "=r"((r)[16]), "=r"((r)[17]), "=r"((r)[18]), "=r"((r)[19]), \
          "=r"((r)[20]), "=r"((r)[21]), "=r"((r)[22]), "=r"((r)[23]), \
          "=r"((r)[24]), "=r"((r)[25]), "=r"((r)[26]), "=r"((r)[27]), \
          "=r"((r)[28]), "=r"((r)[29]), "=r"((r)[30]), "=r"((r)[31]) \
        : "r"(tmem_addr))

static constexpr uint64_t SMEM_DESC_BASE_SW128 =
    (uint64_t(2) << 61) | (uint64_t(1) << 46) | (uint64_t(64) << 32) | (uint64_t(1) << 16);
#define MAKE_SMEM_DESC(base_addr) (SMEM_DESC_BASE_SW128 | ((uint64_t)((base_addr) >> 4) & 0x3FFF))

// idesc: dtype=F32(bit4), atype=BF16(bit7), btype=BF16(bit10), N/8 @17, M/16 @24
#define MMA_IDESC_128x128 ((1u << 4) | (1u << 7) | (1u << 10) | (16u << 17) | (8u << 24))

__device__ __forceinline__ void mma_f16_ss(uint32_t d_tmem, uint64_t a_desc, uint64_t b_desc,
                                           uint32_t idesc, uint32_t enable)
{
    asm volatile(
        "{\n\t.reg .pred p;\n\t"
        "setp.ne.u32 p, %4, 0;\n\t"
        "tcgen05.mma.cta_group::1.kind::f16 [%0], %1, %2, %3, {%5, %5, %5, %5}, p;\n\t"
        "}"
        :: "r"(d_tmem), "l"(a_desc), "l"(b_desc), "r"(idesc), "r"(enable), "r"(0u)
        : "memory");
}
#endif  // HAS_TCGEN05

// ---------------------------------------------------------------------------
// Scratch (device globals; no allocation allowed)
// ---------------------------------------------------------------------------
__device__ float g_proj[(size_t)TOKENS * PROJ];
__device__ float g_dacs[(size_t)TOKENS * NHEADS];
__device__ float g_y[(size_t)TOKENS * DINNER];
__device__ float g_cs[(size_t)BATCH * NCHUNK * NHEADS * DSTATE * HDIM];
__device__ float g_hs[(size_t)BATCH * NCHUNK * NHEADS * DSTATE * HDIM];
__device__ float g_cdecay[(size_t)BATCH * NCHUNK * NHEADS];

__device__ __align__(1024) uint8_t g_xhi[(size_t)TOKENS * DMODEL * 2];
__device__ __align__(1024) uint8_t g_xlo[(size_t)TOKENS * DMODEL * 2];
__device__ __align__(1024) uint8_t g_winhi[(size_t)PROJPAD * DMODEL * 2];
__device__ __align__(1024) uint8_t g_winlo[(size_t)PROJPAD * DMODEL * 2];
__device__ __align__(1024) uint8_t g_wouthi[(size_t)DMODEL * DINNER * 2];
__device__ __align__(1024) uint8_t g_woutlo[(size_t)DMODEL * DINNER * 2];
__device__ __align__(1024) uint8_t g_yghi[(size_t)TOKENS * DINNER * 2];
__device__ __align__(1024) uint8_t g_yglo[(size_t)TOKENS * DINNER * 2];

// ---------------------------------------------------------------------------
// hi/lo split helper
// ---------------------------------------------------------------------------
__device__ __forceinline__ void split4(float4 v, uint2& h, uint2& l)
{
    __nv_bfloat16 hx = __float2bfloat16(v.x), hy = __float2bfloat16(v.y);
    __nv_bfloat16 hz = __float2bfloat16(v.z), hw = __float2bfloat16(v.w);
    __nv_bfloat162 h01 = {hx, hy}, h23 = {hz, hw};
    __nv_bfloat162 l01 = {__float2bfloat16(v.x - __bfloat162float(hx)),
                          __float2bfloat16(v.y - __bfloat162float(hy))};
    __nv_bfloat162 l23 = {__float2bfloat16(v.z - __bfloat162float(hz)),
                          __float2bfloat16(v.w - __bfloat162float(hw))};
    h.x = *reinterpret_cast<uint32_t*>(&h01);
    h.y = *reinterpret_cast<uint32_t*>(&h23);
    l.x = *reinterpret_cast<uint32_t*>(&l01);
    l.y = *reinterpret_cast<uint32_t*>(&l23);
}

// Pack activations (256-row A tiles): src [rows][1024] fp32 -> swizzled blocks
__global__ void __launch_bounds__(256)
split_pack_A(const float* __restrict__ src, uint8_t* __restrict__ hi,
             uint8_t* __restrict__ lo, int n4)
{
    int i = blockIdx.x * 256 + threadIdx.x;
    if (i >= n4) return;
    int t  = i >> 8;
    int k0 = (i & 255) * 4;
    float4 v = reinterpret_cast<const float4*>(src)[i];
    uint2 h, l;
    split4(v, h, l);
    size_t  blk = APK_BLK(t >> 8, k0 >> 6);
    uint32_t off = (uint32_t)((t & 255) * 128 + (k0 & 63) * 2);
    off = SW128(off);
    *reinterpret_cast<uint2*>(hi + blk + off) = h;
    *reinterpret_cast<uint2*>(lo + blk + off) = l;
}

// Pack weights (128-row B tiles) with zero row padding
__global__ void __launch_bounds__(256)
split_pack_B(const float* __restrict__ src, uint8_t* __restrict__ hi,
             uint8_t* __restrict__ lo, int rows_src, int n4)
{
    int i = blockIdx.x * 256 + threadIdx.x;
    if (i >= n4) return;
    int r  = i >> 8;
    int k0 = (i & 255) * 4;
    float4 v = make_float4(0.f, 0.f, 0.f, 0.f);
    if (r < rows_src) v = reinterpret_cast<const float4*>(src)[i];
    uint2 h, l;
    split4(v, h, l);
    size_t  blk = BPK_BLK(r >> 7, k0 >> 6);
    uint32_t off = (uint32_t)((r & 127) * 128 + (k0 & 63) * 2);
    off = SW128(off);
    *reinterpret_cast<uint2*>(hi + blk + off) = h;
    *reinterpret_cast<uint2*>(lo + blk + off) = l;
}

// ---------------------------------------------------------------------------
// tcgen05 bf16-split GEMM, packed operands, cp.async staging.
// Re-phased pipeline: copy(c+1) is issued in iteration c (gated on done(c-1),
// which completed during copy(c)'s stream), so MMA(c) and copy(c+1) overlap.
// 256x128 tile, K-chunks of 64, double-buffered. 256 threads.
// Stage layout: Ahi @0 (32K), Alo @32768, Bhi @65536 (16K), Blo @81920.
// ---------------------------------------------------------------------------
#define STAGE_BYTES 98304
#define GEMM_SMEM_BYTES (2048 + 2 * STAGE_BYTES)

#if HAS_TCGEN05
__device__ __forceinline__ void gemm_copy_chunk(
    uint32_t stage, int tid,
    const uint8_t* __restrict__ Ahi, const uint8_t* __restrict__ Alo,
    const uint8_t* __restrict__ Bhi, const uint8_t* __restrict__ Blo,
    int mt, int nt, int c)
{
    const uint8_t* sAh = Ahi + APK_BLK(mt, c);
    const uint8_t* sAl = Alo + APK_BLK(mt, c);
    const uint8_t* sBh = Bhi + BPK_BLK(nt, c);
    const uint8_t* sBl = Blo + BPK_BLK(nt, c);
#pragma unroll
    for (int it = 0; it < 8; ++it) {
        uint32_t b = (uint32_t)(it * 256 + tid) * 16u;   // 0..32767
        CP_ASYNC16(stage + b,          sAh + b);
        CP_ASYNC16(stage + 32768u + b, sAl + b);
    }
#pragma unroll
    for (int it = 0; it < 4; ++it) {
        uint32_t b = (uint32_t)(it * 256 + tid) * 16u;   // 0..16383
        CP_ASYNC16(stage + 65536u + b, sBh + b);
        CP_ASYNC16(stage + 81920u + b, sBl + b);
    }
    CP_ASYNC_COMMIT();
}
#endif

__global__ void __launch_bounds__(256, 1)
gemm_tc(const uint8_t* __restrict__ Ahi, const uint8_t* __restrict__ Alo,
        const uint8_t* __restrict__ Bhi, const uint8_t* __restrict__ Blo,
        float* __restrict__ C, int NC, int Nstride, int Nout)
{
#if HAS_TCGEN05
    extern __shared__ char smem[];
    const uint32_t sbase = smem_to_u32(smem);
    const int tid = threadIdx.x;
    const int wid = tid >> 5;
    const int lid = tid & 31;
    const int bm = blockIdx.y * 256;
    const int bn = blockIdx.x * 128;

    const uint32_t TMEMP = sbase;
    const uint32_t DONE0 = sbase + 8;
    const uint32_t DONE1 = sbase + 16;
    const uint32_t BUF   = (sbase + 32 + 1023) & ~1023u;

    if (wid == 0) {
        TCGEN05_ALLOC(TMEMP, 256);
        TCGEN05_RELINQUISH();
    }
    if (tid == 0) { MBARRIER_INIT(DONE0, 1); MBARRIER_INIT(DONE1, 1); }
    __syncthreads();
    uint32_t tmem;
    asm volatile("ld.shared.b32 %0, [%1];" : "=r"(tmem) : "r"(TMEMP));

    // prologue: copy chunk 0 only (copy(c+1) is issued inside iteration c)
    gemm_copy_chunk(BUF, tid, Ahi, Alo, Bhi, Blo, blockIdx.y, blockIdx.x, 0);

    for (int c = 0; c < NC; ++c) {
        const int st = c & 1;
        const uint32_t stage = BUF + (uint32_t)st * (uint32_t)STAGE_BYTES;
        const uint32_t done  = st ? DONE1 : DONE0;

        CP_ASYNC_WAIT0();          // copy(c) complete (sole outstanding group)
        __syncthreads();

        if (wid == 0) {
            FENCE_PROXY_ASYNC();
            if (elect_one_pred()) {
                uint64_t dA0h = MAKE_SMEM_DESC(stage);
                uint64_t dA1h = MAKE_SMEM_DESC(stage + 16384);
                uint64_t dA0l = MAKE_SMEM_DESC(stage + 32768);
                uint64_t dA1l = MAKE_SMEM_DESC(stage + 49152);
                uint64_t dBh  = MAKE_SMEM_DESC(stage + 65536);
                uint64_t dBl  = MAKE_SMEM_DESC(stage + 81920);
#pragma unroll
                for (int ks = 0; ks < 4; ++ks) {
                    uint32_t en0 = (c == 0 && ks == 0) ? 0u : 1u;
                    mma_f16_ss(tmem,       dA0h + ks * 2, dBh + ks * 2, MMA_IDESC_128x128, en0);
                    mma_f16_ss(tmem,       dA0h + ks * 2, dBl + ks * 2, MMA_IDESC_128x128, 1u);
                    mma_f16_ss(tmem,       dA0l + ks * 2, dBh + ks * 2, MMA_IDESC_128x128, 1u);
                    mma_f16_ss(tmem + 128, dA1h + ks * 2, dBh + ks * 2, MMA_IDESC_128x128, en0);
                    mma_f16_ss(tmem + 128, dA1h + ks * 2, dBl + ks * 2, MMA_IDESC_128x128, 1u);
                    mma_f16_ss(tmem + 128, dA1l + ks * 2, dBh + ks * 2, MMA_IDESC_128x128, 1u);
                }
                TCGEN05_COMMIT(done);
            }
        }

        // issue copy(c+1) into the other stage; it streams while MMA(c) runs.
        // The other stage held chunk c-1; MMA(c-1) completed during copy(c)'s
        // stream, so this wait is ~free.
        if (c + 1 < NC) {
            if (c >= 1) {
                const uint32_t pdone = ((c - 1) & 1) ? DONE1 : DONE0;
                MBARRIER_WAIT_PARITY(pdone, ((c - 1) >> 1) & 1);
            }
            gemm_copy_chunk(BUF + (uint32_t)((c + 1) & 1) * (uint32_t)STAGE_BYTES,
                            tid, Ahi, Alo, Bhi, Blo, blockIdx.y, blockIdx.x, c + 1);
        }
    }

    MBARRIER_WAIT_PARITY(DONE0, ((NC - 2) >> 1) & 1);
    MBARRIER_WAIT_PARITY(DONE1, ((NC - 1) >> 1) & 1);
    TCGEN05_FENCE_AFTER();

    {
        int mt  = wid >> 2;                       // 0 or 1
        int row = bm + mt * 128 + (wid & 3) * 32 + lid;
        float* crow = C + (size_t)row * Nstride + bn;
        uint32_t tcol = tmem + (uint32_t)(mt * 128);
#pragma unroll
        for (int g = 0; g < 4; ++g) {
            uint32_t r[32];
            TCGEN05_LD_32X32B_X32(r, tcol + g * 32);
            TCGEN05_WAIT_LD();
            int n0 = bn + g * 32;
            if (n0 + 32 <= Nout) {
#pragma unroll
                for (int j = 0; j < 32; j += 4) {
                    float4 v = make_float4(__uint_as_float(r[j]), __uint_as_float(r[j + 1]),
                                           __uint_as_float(r[j + 2]), __uint_as_float(r[j + 3]));
                    *reinterpret_cast<float4*>(crow + g * 32 + j) = v;
                }
            } else {
                for (int j = 0; j < 32; ++j)
                    if (n0 + j < Nout) crow[g * 32 + j] = __uint_as_float(r[j]);
            }
        }
        TCGEN05_FENCE_BEFORE();
    }
    __syncthreads();
    if (wid == 0) TCGEN05_DEALLOC(tmem, 256);

#else   // ---------------- SIMT fallback (generic PTX pass only; never runs) --
    const int tid = threadIdx.x;
    const int bm  = blockIdx.y * 256;
    const int bn  = blockIdx.x * 128;
    const int K   = NC * 64;
    for (int e = tid; e < 256 * 128; e += 256) {
        int i = e >> 7, j = e & 127;
        int m = bm + i, n = bn + j;
        if (n >= Nout) continue;
        float acc = 0.f;
        for (int k = 0; k < K; ++k) {
            size_t ablk = APK_BLK(m >> 8, k >> 6);
            uint32_t aoff = SW128((uint32_t)((m & 255) * 128 + (k & 63) * 2));
            size_t bblk = BPK_BLK(n >> 7, k >> 6);
            uint32_t boff = SW128((uint32_t)((n & 127) * 128 + (k & 63) * 2));
            float a = __bfloat162float(*(const __nv_bfloat16*)(Ahi + ablk + aoff)) +
                      __bfloat162float(*(const __nv_bfloat16*)(Alo + ablk + aoff));
            float b = __bfloat162float(*(const __nv_bfloat16*)(Bhi + bblk + boff)) +
                      __bfloat162float(*(const __nv_bfloat16*)(Blo + bblk + boff));
            acc = fmaf(a, b, acc);
        }
        C[(size_t)m * Nstride + n] = acc;
    }
#endif
}

// ---------------------------------------------------------------------------
// Intra-chunk (dt folded in): dt -> dacs -> scores(T) -> y_intra, chunk_state
// ---------------------------------------------------------------------------
__global__ void __launch_bounds__(256, 3)
intra_kernel(const float* __restrict__ dt_W, const float* __restrict__ dt_b,
             const float* __restrict__ A_log)
{
    const int bid = blockIdx.x;        // (b*NCHUNK + c)*NHEADS + h
    const int h   = bid & 15;
    const int bc  = bid >> 4;
    const int t0  = bc * CHUNK;
    const int tid = threadIdx.x;
    const int wid = tid >> 5;
    const int lid = tid & 31;

    __shared__ float xs[64][68];
    __shared__ float scT[64][68];      // scT[k][i] = scores[i][k]
    __shared__ float Bsh[64][20];
    __shared__ float Csh[64][20];      // reused as bw after scores
    __shared__ float dts[64];
    __shared__ float dacs[64];
    __shared__ float wk[64];

    for (int idx = tid; idx < 64 * 16; idx += 256) {
        int k = idx >> 4, p4 = idx & 15;
        float4 v = *reinterpret_cast<const float4*>(
            g_proj + (size_t)(t0 + k) * PROJ + OFF_XP + h * HDIM + p4 * 4);
        *reinterpret_cast<float4*>(&xs[k][p4 * 4]) = v;
    }
    {
        int k = tid >> 2, n4 = tid & 3;
        float4 vb = *reinterpret_cast<const float4*>(
            g_proj + (size_t)(t0 + k) * PROJ + OFF_B + h * DSTATE + n4 * 4);
        float4 vc = *reinterpret_cast<const float4*>(
            g_proj + (size_t)(t0 + k) * PROJ + OFF_C + h * DSTATE + n4 * 4);
        *reinterpret_cast<float4*>(&Bsh[k][n4 * 4]) = vb;
        *reinterpret_cast<float4*>(&Csh[k][n4 * 4]) = vc;
    }
    if (tid < 64) {
        const float* row = g_proj + (size_t)(t0 + tid) * PROJ + OFF_DT;
        float acc = dt_b[h];
#pragma unroll
        for (int r = 0; r < DTRANK; ++r)
            acc = fmaf(row[r], dt_W[h * DTRANK + r], acc);
        dts[tid] = (acc > 20.f) ? acc : log1pf(expf(acc));
    }
    __syncthreads();

    if (wid == 0) {
        float A  = -expf(A_log[h]);
        float v1 = dts[2 * lid + 1] * A;
        float s  = dts[2 * lid] * A + v1;
#pragma unroll
        for (int off = 1; off < 32; off <<= 1) {
            float t = __shfl_up_sync(0xffffffffu, s, off);
            if (lid >= off) s += t;
        }
        dacs[2 * lid + 1] = s;
        dacs[2 * lid]     = s - v1;
    }
    __syncthreads();

    if (tid < 64) {
        wk[tid] = dts[tid] * expf(dacs[63] - dacs[tid]);
        g_dacs[(size_t)(t0 + tid) * NHEADS + h] = dacs[tid];
    }
    if (tid == 0) g_cdecay[bid] = expf(dacs[63]);
    __syncthreads();

    // scores: thread owns row i = tid&63, columns j0..j0+15; writes transposed
    {
        int i  = tid & 63;
        int j0 = (tid >> 6) * 16;
        float ci[16];
#pragma unroll
        for (int n = 0; n < 16; ++n) ci[n] = Csh[i][n];
        float di = dacs[i];
#pragma unroll
        for (int jj = 0; jj < 16; ++jj) {
            int j = j0 + jj;
            float v = 0.f;
            if (j <= i) {
                float d = 0.f;
#pragma unroll
                for (int n = 0; n < 16; ++n)
                    d = fmaf(ci[n], Bsh[j][n], d);
                v = d * expf(di - dacs[j]) * dts[j];
            }
            scT[j][i] = v;
        }
    }
    __syncthreads();

    // bw[k][n] = B[k][n] * wk[k]  (overwrite Csh, dead after scores)
    for (int idx = tid; idx < 64 * 16; idx += 256) {
        int k = idx >> 4, n = idx & 15;
        Csh[k][n] = Bsh[k][n] * wk[k];
    }
    __syncthreads();

    // y_intra: 4x4 register blocking, causal-truncated k loop, float4 LDS both
    {
        int a  = tid >> 4;
        int b  = tid & 15;
        int i0 = a * 4, p0 = b * 4;
        float acc[4][4];
#pragma unroll
        for (int q = 0; q < 4; ++q)
#pragma unroll
            for (int r = 0; r < 4; ++r) acc[q][r] = 0.f;
        const int kmax = i0 + 4;          // scT[k][i] = 0 for k > i
        for (int kk = 0; kk < kmax; ++kk) {
            float4 s4 = *reinterpret_cast<const float4*>(&scT[kk][i0]);
            float4 xr = *reinterpret_cast<const float4*>(&xs[kk][p0]);
            acc[0][0] = fmaf(s4.x, xr.x, acc[0][0]);
            acc[0][1] = fmaf(s4.x, xr.y, acc[0][1]);
            acc[0][2] = fmaf(s4.x, xr.z, acc[0][2]);
            acc[0][3] = fmaf(s4.x, xr.w, acc[0][3]);
            acc[1][0] = fmaf(s4.y, xr.x, acc[1][0]);
            acc[1][1] = fmaf(s4.y, xr.y, acc[1][1]);
            acc[1][2] = fmaf(s4.y, xr.z, acc[1][2]);
            acc[1][3] = fmaf(s4.y, xr.w, acc[1][3]);
            acc[2][0] = fmaf(s4.z, xr.x, acc[2][0]);
            acc[2][1] = fmaf(s4.z, xr.y, acc[2][1]);
            acc[2][2] = fmaf(s4.z, xr.z, acc[2][2]);
            acc[2][3] = fmaf(s4.z, xr.w, acc[2][3]);
            acc[3][0] = fmaf(s4.w, xr.x, acc[3][0]);
            acc[3][1] = fmaf(s4.w, xr.y, acc[3][1]);
            acc[3][2] = fmaf(s4.w, xr.z, acc[3][2]);
            acc[3][3] = fmaf(s4.w, xr.w, acc[3][3]);
        }
#pragma unroll
        for (int q = 0; q < 4; ++q) {
            float4 v = make_float4(acc[q][0], acc[q][1], acc[q][2], acc[q][3]);
            *reinterpret_cast<float4*>(
                g_y + (size_t)(t0 + i0 + q) * DINNER + h * HDIM + p0) = v;
        }
    }

    // chunk_state[n][p] = sum_k bw[k][n] * x[k][p]
    {
        int n  = tid >> 4;
        int p0 = (tid & 15) * 4;
        float4 acc = make_float4(0.f, 0.f, 0.f, 0.f);
        for (int k = 0; k < 64; ++k) {
            float bwv = Csh[k][n];
            float4 xr = *reinterpret_cast<const float4*>(&xs[k][p0]);
            acc.x = fmaf(bwv, xr.x, acc.x);
            acc.y = fmaf(bwv, xr.y, acc.y);
            acc.z = fmaf(bwv, xr.z, acc.z);
            acc.w = fmaf(bwv, xr.w, acc.w);
        }
        *reinterpret_cast<float4*>(
            g_cs + (size_t)bid * (DSTATE * HDIM) + n * HDIM + p0) = acc;
    }
}

// ---------------------------------------------------------------------------
// Sequential scan over chunks: grid = BATCH*NHEADS*4, 1 elem/thread
// ---------------------------------------------------------------------------
__global__ void __launch_bounds__(256)
scan_kernel()
{
    const int g   = blockIdx.x;
    const int bh  = g >> 2;
    const int seg = g & 3;
    const int b   = bh >> 4;
    const int h   = bh & 15;
    const int e   = seg * 256 + threadIdx.x;

    const int    chid0  = (b * NCHUNK) * NHEADS + h;
    const size_t base   = (size_t)chid0 * (DSTATE * HDIM);
    const size_t stride = (size_t)NHEADS * DSTATE * HDIM;

    float hv  = 0.f;
    float cur = g_cs[base + e];
    float d   = g_cdecay[chid0];
    for (int c = 0; c < NCHUNK; ++c) {
        float nxt = 0.f, dn = 0.f;
        if (c + 1 < NCHUNK) {
            nxt = g_cs[base + stride * (c + 1) + e];
            dn  = g_cdecay[chid0 + (c + 1) * NHEADS];
        }
        g_hs[base + stride * c + e] = hv;
        hv = fmaf(d, hv, cur);
        cur = nxt; d = dn;
    }
}

// ---------------------------------------------------------------------------
// Cross-chunk + skip
// ---------------------------------------------------------------------------
__global__ void __launch_bounds__(256, 2)
cross_kernel(const float* __restrict__ D_param)
{
    const int bid = blockIdx.x;
    const int h   = bid & 15;
    const int bc  = bid >> 4;
    const int t0  = bc * CHUNK;
    const int tid = threadIdx.x;

    __shared__ float hs[16][68];
    __shared__ float Csh[64][20];
    __shared__ float dacs[64];

    {
        int n = tid >> 4, pg = tid & 15;
        float4 v = *reinterpret_cast<const float4*>(
            g_hs + (size_t)bid * (DSTATE * HDIM) + n * HDIM + pg * 4);
        *reinterpret_cast<float4*>(&hs[n][pg * 4]) = v;
    }
    {
        int k = tid >> 2, n4 = tid & 3;
        float4 vc = *reinterpret_cast<const float4*>(
            g_proj + (size_t)(t0 + k) * PROJ + OFF_C + h * DSTATE + n4 * 4);
        *reinterpret_cast<float4*>(&Csh[k][n4 * 4]) = vc;
    }
    if (tid < 64) dacs[tid] = g_dacs[(size_t)(t0 + tid) * NHEADS + h];
    __syncthreads();

    int i  = tid >> 2;
    int p0 = (tid & 3) * 16;
    float ci[16];
#pragma unroll
    for (int n = 0; n < 16; ++n) ci[n] = Csh[i][n];
    float e  = expf(dacs[i]);
    float dp = D_param[h];

    size_t t = (size_t)(t0 + i);
    const float* xrow = g_proj + t * PROJ + OFF_XP + h * HDIM;
    float* yrow = g_y + t * DINNER + h * HDIM;
#pragma unroll
    for (int g4 = 0; g4 < 4; ++g4) {
        int p = p0 + g4 * 4;
        float4 yv = *reinterpret_cast<const float4*>(yrow + p);
        float4 xv = *reinterpret_cast<const float4*>(xrow + p);
        float a0 = 0.f, a1 = 0.f, a2 = 0.f, a3 = 0.f;
#pragma unroll
        for (int n = 0; n < 16; ++n) {
            float c = ci[n];
            a0 = fmaf(c, hs[n][p + 0], a0);
            a1 = fmaf(c, hs[n][p + 1], a1);
            a2 = fmaf(c, hs[n][p + 2], a2);
            a3 = fmaf(c, hs[n][p + 3], a3);
        }
        float4 o;
        o.x = yv.x + e * a0 + dp * xv.x;
        o.y = yv.y + e * a1 + dp * xv.y;
        o.z = yv.z + e * a2 + dp * xv.z;
        o.w = yv.w + e * a3 + dp * xv.w;
        *reinterpret_cast<float4*>(yrow + p) = o;
    }
}

// ---------------------------------------------------------------------------
// RMS norm + SiLU gate -> yg packed (bf16 hi/lo, swizzled A-tile layout)
// ---------------------------------------------------------------------------
__global__ void __launch_bounds__(256)
norm_kernel(const float* __restrict__ norm_w)
{
    const int t   = blockIdx.x;
    const int tid = threadIdx.x;

    float4 v = reinterpret_cast<const float4*>(g_y + (size_t)t * DINNER)[tid];
    float ss = v.x * v.x + v.y * v.y + v.z * v.z + v.w * v.w;
#pragma unroll
    for (int off = 16; off > 0; off >>= 1)
        ss += __shfl_xor_sync(0xffffffffu, ss, off);

    __shared__ float red[8];
    __shared__ float s_inv;
    if ((tid & 31) == 0) red[tid >> 5] = ss;
    __syncthreads();
    if (tid == 0) {
        float s = 0.f;
#pragma unroll
        for (int i = 0; i < 8; ++i) s += red[i];
        s_inv = rsqrtf(s * (1.f / DINNER) + 1e-6f);
    }
    __syncthreads();
    float inv = s_inv;

    const float* zrow = g_proj + (size_t)t * PROJ + OFF_Z;
    int c = tid * 4;
    float4 z4 = *reinterpret_cast<const float4*>(zrow + c);
    float4 w4 = *reinterpret_cast<const float4*>(norm_w + c);
    float4 o;
    o.x = v.x * inv * w4.x * (z4.x / (1.f + expf(-z4.x)));
    o.y = v.y * inv * w4.y * (z4.y / (1.f + expf(-z4.y)));
    o.z = v.z * inv * w4.z * (z4.z / (1.f + expf(-z4.z)));
    o.w = v.w * inv * w4.w * (z4.w / (1.f + expf(-z4.w)));

    uint2 h, l;
    split4(o, h, l);
    size_t  blk = APK_BLK(t >> 8, c >> 6);
    uint32_t off = (uint32_t)((t & 255) * 128 + (c & 63) * 2);
    off = SW128(off);
    *reinterpret_cast<uint2*>(g_yghi + blk + off) = h;
    *reinterpret_cast<uint2*>(g_yglo + blk + off) = l;
}

// ---------------------------------------------------------------------------
// Launch — proj GEMM at slot #4 (profiled)
// ---------------------------------------------------------------------------
extern "C" void kernel_launch(void* const* d_in, const int* in_sizes, int n_in,
                              void* d_out, int out_size)
{
    const float* x      = (const float*)d_in[0];
    const float* W_in   = (const float*)d_in[1];
    const float* dt_W   = (const float*)d_in[2];
    const float* dt_b   = (const float*)d_in[3];
    const float* A_log  = (const float*)d_in[4];
    const float* D_par  = (const float*)d_in[5];
    const float* W_out  = (const float*)d_in[6];
    const float* norm_w = (const float*)d_in[7];
    float* out = (float*)d_out;

    float* proj_ptr = nullptr;
    uint8_t *xhi, *xlo, *winhi, *winlo, *wouthi, *woutlo, *yghi, *yglo;
    cudaGetSymbolAddress((void**)&proj_ptr, g_proj);
    cudaGetSymbolAddress((void**)&xhi, g_xhi);
    cudaGetSymbolAddress((void**)&xlo, g_xlo);
    cudaGetSymbolAddress((void**)&winhi, g_winhi);
    cudaGetSymbolAddress((void**)&winlo, g_winlo);
    cudaGetSymbolAddress((void**)&wouthi, g_wouthi);
    cudaGetSymbolAddress((void**)&woutlo, g_woutlo);
    cudaGetSymbolAddress((void**)&yghi, g_yghi);
    cudaGetSymbolAddress((void**)&yglo, g_yglo);

    cudaFuncSetAttribute(gemm_tc, cudaFuncAttributeMaxDynamicSharedMemorySize, GEMM_SMEM_BYTES);

    // 1) pack x
    {
        int n4 = TOKENS * DMODEL / 4;
        split_pack_A<<<(n4 + 255) / 256, 256>>>(x, xhi, xlo, n4);
    }
    // 2) pack W_in (padded to 2688 rows)
    {
        int n4 = PROJPAD * DMODEL / 4;
        split_pack_B<<<(n4 + 255) / 256, 256>>>(W_in, winhi, winlo, PROJ, n4);
    }
    // 3) pack W_out
    {
        int n4 = DMODEL * DINNER / 4;
        split_pack_B<<<(n4 + 255) / 256, 256>>>(W_out, wouthi, woutlo, DMODEL, n4);
    }
    // 4) proj = x @ W_in^T   [16384, 2576]   <- profiled slot
    {
        dim3 grid(PROJPAD / 128, TOKENS / 256);
        gemm_tc<<<grid, 256, GEMM_SMEM_BYTES>>>(xhi, xlo, winhi, winlo,
                                                proj_ptr, DMODEL / 64, PROJ, PROJ);
    }
    // 5) intra-chunk (+dt)
    intra_kernel<<<BATCH * NCHUNK * NHEADS, 256>>>(dt_W, dt_b, A_log);
    // 6) chunk scan
    scan_kernel<<<BATCH * NHEADS * 4, 256>>>();
    // 7) cross-chunk + skip
    cross_kernel<<<BATCH * NCHUNK * NHEADS, 256>>>(D_par);
    // 8) RMS norm + gate -> packed bf16 hi/lo
    norm_kernel<<<TOKENS, 256>>>(norm_w);
    // 9) out = yg @ W_out^T  [16384, 1024]
    {
        dim3 grid(DMODEL / 128, TOKENS / 256);
        gemm_tc<<<grid, 256, GEMM_SMEM_BYTES>>>(yghi, yglo, wouthi, woutlo,
                                                out, DINNER / 64, DMODEL, DMODEL);
    }
}

// round 14
// speedup vs baseline: 1.0472x; 1.0472x over previous
#include <cuda_runtime.h>
#include <cuda_bf16.h>
#include <cstdint>

// ---------------------------------------------------------------------------
// Problem constants
// ---------------------------------------------------------------------------
#define BATCH   4
#define SEQ     4096
#define TOKENS  (BATCH * SEQ)        // 16384
#define DMODEL  1024
#define DINNER  1024
#define NHEADS  16
#define HDIM    64
#define DSTATE  16
#define DTRANK  16
#define CHUNK   64
#define NCHUNK  (SEQ / CHUNK)        // 64
#define PROJ    2576
#define PROJPAD 2688                 // 21 * 128

#define OFF_XP   0
#define OFF_Z    1024
#define OFF_B    2048
#define OFF_C    2304
#define OFF_DT   2560

// Packed-operand block offsets (bytes). A-pack: 256-row tiles; B-pack: 128-row.
// Both GEMMs have K=1024 -> exactly 16 chunks of 64 columns.
#define APK_BLK(mt, ch) ((((size_t)(mt) * 16) + (size_t)(ch)) * 32768)
#define BPK_BLK(nt, ch) ((((size_t)(nt) * 16) + (size_t)(ch)) * 16384)
#define SW128(o) ((o) ^ (((o) >> 3) & 0x70))

// tcgen05 is an arch-SPECIFIC feature: only emit it in the sm_103a/f passes.
#if defined(__CUDA_ARCH_FEAT_SM103_ALL) || \
    (defined(__CUDA_ARCH_FAMILY_SPECIFIC__) && __CUDA_ARCH_FAMILY_SPECIFIC__ >= 1000) || \
    (defined(__CUDA_ARCH_SPECIFIC__) && __CUDA_ARCH_SPECIFIC__ >= 1000)
#define HAS_TCGEN05 1
#else
#define HAS_TCGEN05 0
#endif

// ---------------------------------------------------------------------------
// PTX helpers (guarded)
// ---------------------------------------------------------------------------
#if HAS_TCGEN05
__device__ __forceinline__ uint32_t smem_to_u32(const void* p) {
    uint32_t a;
    asm("{ .reg .u64 t; cvta.to.shared.u64 t, %1; cvt.u32.u64 %0, t; }" : "=r"(a) : "l"(p));
    return a;
}
__device__ __forceinline__ uint32_t elect_one_pred() {
    uint32_t pred;
    asm volatile("{\n\t.reg .pred p;\n\telect.sync _|p, 0xFFFFFFFF;\n\tselp.b32 %0, 1, 0, p;\n\t}" : "=r"(pred));
    return pred;
}
#define TCGEN05_ALLOC(smem_result_addr, nCols) \
    asm volatile("tcgen05.alloc.cta_group::1.sync.aligned.shared::cta.b32 [%0], %1;" \
        :: "r"((uint32_t)(smem_result_addr)), "r"((uint32_t)(nCols)) : "memory")
#define TCGEN05_DEALLOC(tmem_addr, nCols) \
    asm volatile("tcgen05.dealloc.cta_group::1.sync.aligned.b32 %0, %1;" :: "r"(tmem_addr), "r"((uint32_t)(nCols)))
#define TCGEN05_RELINQUISH() \
    asm volatile("tcgen05.relinquish_alloc_permit.cta_group::1.sync.aligned;")
#define TCGEN05_COMMIT(mbar) \
    asm volatile("tcgen05.commit.cta_group::1.mbarrier::arrive::one.shared::cluster.b64 [%0];" \
        :: "r"((uint32_t)(mbar)) : "memory")
#define TCGEN05_FENCE_AFTER()  asm volatile("tcgen05.fence::after_thread_sync;" ::: "memory")
#define TCGEN05_FENCE_BEFORE() asm volatile("tcgen05.fence::before_thread_sync;" ::: "memory")
#define TCGEN05_WAIT_LD()      asm volatile("tcgen05.wait::ld.sync.aligned;" ::: "memory")
#define MBARRIER_INIT(mbar, count) \
    asm volatile("mbarrier.init.shared.b64 [%0], %1;" :: "r"((uint32_t)(mbar)), "r"((uint32_t)(count)) : "memory")
#define FENCE_PROXY_ASYNC() asm volatile("fence.proxy.async.shared::cta;" ::: "memory")
#define CP_ASYNC16(dst, src) \
    asm volatile("cp.async.cg.shared.global [%0], [%1], 16;" \
        :: "r"((uint32_t)(dst)), "l"(src) : "memory")
#define CP_ASYNC_COMMIT() asm volatile("cp.async.commit_group;" ::: "memory")
#define CP_ASYNC_WAIT0()  asm volatile("cp.async.wait_group 0;" ::: "memory")
#define CP_ASYNC_WAIT1()  asm volatile("cp.async.wait_group 1;" ::: "memory")
#define MBARRIER_WAIT_PARITY(mbar, parity) do { \
    uint32_t _m = (uint32_t)(mbar); uint32_t _p = (uint32_t)(parity); uint32_t _d; \
    asm volatile("{\n\t.reg .pred p;\n\t" \
        "mbarrier.try_wait.parity.acquire.cta.shared::cta.b64 p, [%1], %2;\n\t" \
        "selp.b32 %0, 1, 0, p;\n\t}" : "=r"(_d) : "r"(_m), "r"(_p) : "memory"); \
    if (!_d) { \
        asm volatile("{\n\t.reg .pred P1;\n\t" \
            "WL_%=:\n\t" \
            "mbarrier.try_wait.parity.acquire.cta.shared::cta.b64 P1, [%0], %1, 0x989680;\n\t" \
            "@P1 bra.uni WD_%=;\n\t" \
            "bra.uni WL_%=;\n\t" \
            "WD_%=:\n\t}" :: "r"(_m), "r"(_p) : "memory"); \
    } } while (0)
#define TCGEN05_LD_32X32B_X32(r, tmem_addr) \
    asm volatile("tcgen05.ld.sync.aligned.32x32b.x32.b32 " \
        "{%0, %1, %2, %3, %4, %5, %6, %7, %8, %9, %10, %11, %12, %13, %14, %15, " \
        " %16, %17, %18, %19, %20, %21, %22, %23, %24, %25, %26, %27, %28, %29, %30, %31}, [%32];" \
        : "=r"((r)[0]),  "=r"((r)[1]),  "=r"((r)[2]),  "=r"((r)[3]), \
          "=r"((r)[4]),  "=r"((r)[5]),  "=r"((r)[6]),  "=r"((r)[7]), \
          "=r"((r)[8]),  "=r"((r)[9]),  "=r"((r)[10]), "=r"((r)[11]), \
          "=r"((r)[12]), "=r"((r)[13]), "=r"((r)[14]), "=r"((r)[15]), \
          "=r"((r)[16]), "=r"((r)[17]), "=r"((r)[18]), "=r"((r)[19]), \
          "=r"((r)[20]), "=r"((r)[21]), "=r"((r)[22]), "=r"((r)[23]), \
          "=r"((r)[24]), "=r"((r)[25]), "=r"((r)[26]), "=r"((r)[27]), \
          "=r"((r)[28]), "=r"((r)[29]), "=r"((r)[30]), "=r"((r)[31]) \
        : "r"(tmem_addr))

static constexpr uint64_t SMEM_DESC_BASE_SW128 =
    (uint64_t(2) << 61) | (uint64_t(1) << 46) | (uint64_t(64) << 32) | (uint64_t(1) << 16);
#define MAKE_SMEM_DESC(base_addr) (SMEM_DESC_BASE_SW128 | ((uint64_t)((base_addr) >> 4) & 0x3FFF))

// idesc: dtype=F32(bit4), atype=BF16(bit7), btype=BF16(bit10), N/8 @17, M/16 @24
#define MMA_IDESC_128x128 ((1u << 4) | (1u << 7) | (1u << 10) | (16u << 17) | (8u << 24))

__device__ __forceinline__ void mma_f16_ss(uint32_t d_tmem, uint64_t a_desc, uint64_t b_desc,
                                           uint32_t idesc, uint32_t enable)
{
    asm volatile(
        "{\n\t.reg .pred p;\n\t"
        "setp.ne.u32 p, %4, 0;\n\t"
        "tcgen05.mma.cta_group::1.kind::f16 [%0], %1, %2, %3, {%5, %5, %5, %5}, p;\n\t"
        "}"
        :: "r"(d_tmem), "l"(a_desc), "l"(b_desc), "r"(idesc), "r"(enable), "r"(0u)
        : "memory");
}
#endif  // HAS_TCGEN05

// ---------------------------------------------------------------------------
// Scratch (device globals; no allocation allowed)
// ---------------------------------------------------------------------------
__device__ float g_proj[(size_t)TOKENS * PROJ];
__device__ float g_dacs[(size_t)TOKENS * NHEADS];
__device__ float g_y[(size_t)TOKENS * DINNER];
__device__ float g_cs[(size_t)BATCH * NCHUNK * NHEADS * DSTATE * HDIM];
__device__ float g_hs[(size_t)BATCH * NCHUNK * NHEADS * DSTATE * HDIM];
__device__ float g_cdecay[(size_t)BATCH * NCHUNK * NHEADS];

__device__ __align__(1024) uint8_t g_xhi[(size_t)TOKENS * DMODEL * 2];
__device__ __align__(1024) uint8_t g_xlo[(size_t)TOKENS * DMODEL * 2];
__device__ __align__(1024) uint8_t g_winhi[(size_t)PROJPAD * DMODEL * 2];
__device__ __align__(1024) uint8_t g_winlo[(size_t)PROJPAD * DMODEL * 2];
__device__ __align__(1024) uint8_t g_wouthi[(size_t)DMODEL * DINNER * 2];
__device__ __align__(1024) uint8_t g_woutlo[(size_t)DMODEL * DINNER * 2];
__device__ __align__(1024) uint8_t g_yghi[(size_t)TOKENS * DINNER * 2];
__device__ __align__(1024) uint8_t g_yglo[(size_t)TOKENS * DINNER * 2];

// ---------------------------------------------------------------------------
// hi/lo split helper
// ---------------------------------------------------------------------------
__device__ __forceinline__ void split4(float4 v, uint2& h, uint2& l)
{
    __nv_bfloat16 hx = __float2bfloat16(v.x), hy = __float2bfloat16(v.y);
    __nv_bfloat16 hz = __float2bfloat16(v.z), hw = __float2bfloat16(v.w);
    __nv_bfloat162 h01 = {hx, hy}, h23 = {hz, hw};
    __nv_bfloat162 l01 = {__float2bfloat16(v.x - __bfloat162float(hx)),
                          __float2bfloat16(v.y - __bfloat162float(hy))};
    __nv_bfloat162 l23 = {__float2bfloat16(v.z - __bfloat162float(hz)),
                          __float2bfloat16(v.w - __bfloat162float(hw))};
    h.x = *reinterpret_cast<uint32_t*>(&h01);
    h.y = *reinterpret_cast<uint32_t*>(&h23);
    l.x = *reinterpret_cast<uint32_t*>(&l01);
    l.y = *reinterpret_cast<uint32_t*>(&l23);
}

// Pack activations (256-row A tiles): src [rows][1024] fp32 -> swizzled blocks
__global__ void __launch_bounds__(256)
split_pack_A(const float* __restrict__ src, uint8_t* __restrict__ hi,
             uint8_t* __restrict__ lo, int n4)
{
    int i = blockIdx.x * 256 + threadIdx.x;
    if (i >= n4) return;
    int t  = i >> 8;
    int k0 = (i & 255) * 4;
    float4 v = reinterpret_cast<const float4*>(src)[i];
    uint2 h, l;
    split4(v, h, l);
    size_t  blk = APK_BLK(t >> 8, k0 >> 6);
    uint32_t off = (uint32_t)((t & 255) * 128 + (k0 & 63) * 2);
    off = SW128(off);
    *reinterpret_cast<uint2*>(hi + blk + off) = h;
    *reinterpret_cast<uint2*>(lo + blk + off) = l;
}

// Pack weights (128-row B tiles) with zero row padding
__global__ void __launch_bounds__(256)
split_pack_B(const float* __restrict__ src, uint8_t* __restrict__ hi,
             uint8_t* __restrict__ lo, int rows_src, int n4)
{
    int i = blockIdx.x * 256 + threadIdx.x;
    if (i >= n4) return;
    int r  = i >> 8;
    int k0 = (i & 255) * 4;
    float4 v = make_float4(0.f, 0.f, 0.f, 0.f);
    if (r < rows_src) v = reinterpret_cast<const float4*>(src)[i];
    uint2 h, l;
    split4(v, h, l);
    size_t  blk = BPK_BLK(r >> 7, k0 >> 6);
    uint32_t off = (uint32_t)((r & 127) * 128 + (k0 & 63) * 2);
    off = SW128(off);
    *reinterpret_cast<uint2*>(hi + blk + off) = h;
    *reinterpret_cast<uint2*>(lo + blk + off) = l;
}

// ---------------------------------------------------------------------------
// tcgen05 bf16-split GEMM, packed operands, cp.async staging.
// Re-ordered 2-stage schedule (all-threads, no warp specialization):
//   iter c: wait done(c-1) -> issue copy(c+1) -> wait_group 1 (copy(c) done,
//   issued a full iteration ago) -> sync -> MMA(c) + commit done(c).
// The done-wait overlaps the previous copy's stream; copy(c) gets ~1 MMA of
// lead. Every thread walks every done phase in order (parity-safe drains).
// 256x128 tile, K-chunks of 64, double-buffered. 256 threads.
// Stage layout: Ahi @0 (32K), Alo @32768, Bhi @65536 (16K), Blo @81920.
// ---------------------------------------------------------------------------
#define STAGE_BYTES 98304
#define GEMM_SMEM_BYTES (2048 + 2 * STAGE_BYTES)

#if HAS_TCGEN05
__device__ __forceinline__ void gemm_copy_chunk(
    uint32_t stage, int tid,
    const uint8_t* __restrict__ Ahi, const uint8_t* __restrict__ Alo,
    const uint8_t* __restrict__ Bhi, const uint8_t* __restrict__ Blo,
    int mt, int nt, int c)
{
    const uint8_t* sAh = Ahi + APK_BLK(mt, c);
    const uint8_t* sAl = Alo + APK_BLK(mt, c);
    const uint8_t* sBh = Bhi + BPK_BLK(nt, c);
    const uint8_t* sBl = Blo + BPK_BLK(nt, c);
#pragma unroll
    for (int it = 0; it < 8; ++it) {
        uint32_t b = (uint32_t)(it * 256 + tid) * 16u;   // 0..32767
        CP_ASYNC16(stage + b,          sAh + b);
        CP_ASYNC16(stage + 32768u + b, sAl + b);
    }
#pragma unroll
    for (int it = 0; it < 4; ++it) {
        uint32_t b = (uint32_t)(it * 256 + tid) * 16u;   // 0..16383
        CP_ASYNC16(stage + 65536u + b, sBh + b);
        CP_ASYNC16(stage + 81920u + b, sBl + b);
    }
    CP_ASYNC_COMMIT();
}
#endif

__global__ void __launch_bounds__(256, 1)
gemm_tc(const uint8_t* __restrict__ Ahi, const uint8_t* __restrict__ Alo,
        const uint8_t* __restrict__ Bhi, const uint8_t* __restrict__ Blo,
        float* __restrict__ C, int NC, int Nstride, int Nout)
{
#if HAS_TCGEN05
    extern __shared__ char smem[];
    const uint32_t sbase = smem_to_u32(smem);
    const int tid = threadIdx.x;
    const int wid = tid >> 5;
    const int lid = tid & 31;
    const int bm = blockIdx.y * 256;
    const int bn = blockIdx.x * 128;

    const uint32_t TMEMP = sbase;
    const uint32_t DONE0 = sbase + 8;
    const uint32_t DONE1 = sbase + 16;
    const uint32_t BUF   = (sbase + 32 + 1023) & ~1023u;

    if (wid == 0) {
        TCGEN05_ALLOC(TMEMP, 256);
        TCGEN05_RELINQUISH();
    }
    if (tid == 0) { MBARRIER_INIT(DONE0, 1); MBARRIER_INIT(DONE1, 1); }
    __syncthreads();
    uint32_t tmem;
    asm volatile("ld.shared.b32 %0, [%1];" : "=r"(tmem) : "r"(TMEMP));

    // prologue: copy chunk 0
    gemm_copy_chunk(BUF, tid, Ahi, Alo, Bhi, Blo, blockIdx.y, blockIdx.x, 0);

    for (int c = 0; c < NC; ++c) {
        const int st = c & 1;
        const uint32_t stage = BUF + (uint32_t)st * (uint32_t)STAGE_BYTES;
        const uint32_t done  = st ? DONE1 : DONE0;

        if (c + 1 < NC) {
            // free the other stage: MMA(c-1) must have finished reading it
            if (c >= 1) {
                const uint32_t pdone = ((c - 1) & 1) ? DONE1 : DONE0;
                MBARRIER_WAIT_PARITY(pdone, ((c - 1) >> 1) & 1);
            }
            gemm_copy_chunk(BUF + (uint32_t)((c + 1) & 1) * (uint32_t)STAGE_BYTES,
                            tid, Ahi, Alo, Bhi, Blo, blockIdx.y, blockIdx.x, c + 1);
            CP_ASYNC_WAIT1();      // copy(c) complete; copy(c+1) still streaming
        } else {
            CP_ASYNC_WAIT0();      // last chunk: only copy(c) outstanding
        }
        __syncthreads();

        if (wid == 0) {
            FENCE_PROXY_ASYNC();
            if (elect_one_pred()) {
                uint64_t dA0h = MAKE_SMEM_DESC(stage);
                uint64_t dA1h = MAKE_SMEM_DESC(stage + 16384);
                uint64_t dA0l = MAKE_SMEM_DESC(stage + 32768);
                uint64_t dA1l = MAKE_SMEM_DESC(stage + 49152);
                uint64_t dBh  = MAKE_SMEM_DESC(stage + 65536);
                uint64_t dBl  = MAKE_SMEM_DESC(stage + 81920);
#pragma unroll
                for (int ks = 0; ks < 4; ++ks) {
                    uint32_t en0 = (c == 0 && ks == 0) ? 0u : 1u;
                    mma_f16_ss(tmem,       dA0h + ks * 2, dBh + ks * 2, MMA_IDESC_128x128, en0);
                    mma_f16_ss(tmem,       dA0h + ks * 2, dBl + ks * 2, MMA_IDESC_128x128, 1u);
                    mma_f16_ss(tmem,       dA0l + ks * 2, dBh + ks * 2, MMA_IDESC_128x128, 1u);
                    mma_f16_ss(tmem + 128, dA1h + ks * 2, dBh + ks * 2, MMA_IDESC_128x128, en0);
                    mma_f16_ss(tmem + 128, dA1h + ks * 2, dBl + ks * 2, MMA_IDESC_128x128, 1u);
                    mma_f16_ss(tmem + 128, dA1l + ks * 2, dBh + ks * 2, MMA_IDESC_128x128, 1u);
                }
                TCGEN05_COMMIT(done);
            }
        }
    }

    MBARRIER_WAIT_PARITY(DONE0, ((NC - 2) >> 1) & 1);
    MBARRIER_WAIT_PARITY(DONE1, ((NC - 1) >> 1) & 1);
    TCGEN05_FENCE_AFTER();

    {
        int mt  = wid >> 2;                       // 0 or 1
        int row = bm + mt * 128 + (wid & 3) * 32 + lid;
        float* crow = C + (size_t)row * Nstride + bn;
        uint32_t tcol = tmem + (uint32_t)(mt * 128);
#pragma unroll
        for (int g = 0; g < 4; ++g) {
            uint32_t r[32];
            TCGEN05_LD_32X32B_X32(r, tcol + g * 32);
            TCGEN05_WAIT_LD();
            int n0 = bn + g * 32;
            if (n0 + 32 <= Nout) {
#pragma unroll
                for (int j = 0; j < 32; j += 4) {
                    float4 v = make_float4(__uint_as_float(r[j]), __uint_as_float(r[j + 1]),
                                           __uint_as_float(r[j + 2]), __uint_as_float(r[j + 3]));
                    *reinterpret_cast<float4*>(crow + g * 32 + j) = v;
                }
            } else {
                for (int j = 0; j < 32; ++j)
                    if (n0 + j < Nout) crow[g * 32 + j] = __uint_as_float(r[j]);
            }
        }
        TCGEN05_FENCE_BEFORE();
    }
    __syncthreads();
    if (wid == 0) TCGEN05_DEALLOC(tmem, 256);

#else   // ---------------- SIMT fallback (generic PTX pass only; never runs) --
    const int tid = threadIdx.x;
    const int bm  = blockIdx.y * 256;
    const int bn  = blockIdx.x * 128;
    const int K   = NC * 64;
    for (int e = tid; e < 256 * 128; e += 256) {
        int i = e >> 7, j = e & 127;
        int m = bm + i, n = bn + j;
        if (n >= Nout) continue;
        float acc = 0.f;
        for (int k = 0; k < K; ++k) {
            size_t ablk = APK_BLK(m >> 8, k >> 6);
            uint32_t aoff = SW128((uint32_t)((m & 255) * 128 + (k & 63) * 2));
            size_t bblk = BPK_BLK(n >> 7, k >> 6);
            uint32_t boff = SW128((uint32_t)((n & 127) * 128 + (k & 63) * 2));
            float a = __bfloat162float(*(const __nv_bfloat16*)(Ahi + ablk + aoff)) +
                      __bfloat162float(*(const __nv_bfloat16*)(Alo + ablk + aoff));
            float b = __bfloat162float(*(const __nv_bfloat16*)(Bhi + bblk + boff)) +
                      __bfloat162float(*(const __nv_bfloat16*)(Blo + bblk + boff));
            acc = fmaf(a, b, acc);
        }
        C[(size_t)m * Nstride + n] = acc;
    }
#endif
}

// ---------------------------------------------------------------------------
// Intra-chunk (dt folded in): dt -> dacs -> scores(T) -> y_intra, chunk_state
// ---------------------------------------------------------------------------
__global__ void __launch_bounds__(256, 3)
intra_kernel(const float* __restrict__ dt_W, const float* __restrict__ dt_b,
             const float* __restrict__ A_log)
{
    const int bid = blockIdx.x;        // (b*NCHUNK + c)*NHEADS + h
    const int h   = bid & 15;
    const int bc  = bid >> 4;
    const int t0  = bc * CHUNK;
    const int tid = threadIdx.x;
    const int wid = tid >> 5;
    const int lid = tid & 31;

    __shared__ float xs[64][68];
    __shared__ float scT[64][68];      // scT[k][i] = scores[i][k]
    __shared__ float Bsh[64][20];
    __shared__ float Csh[64][20];      // reused as bw after scores
    __shared__ float dts[64];
    __shared__ float dacs[64];
    __shared__ float wk[64];

    for (int idx = tid; idx < 64 * 16; idx += 256) {
        int k = idx >> 4, p4 = idx & 15;
        float4 v = *reinterpret_cast<const float4*>(
            g_proj + (size_t)(t0 + k) * PROJ + OFF_XP + h * HDIM + p4 * 4);
        *reinterpret_cast<float4*>(&xs[k][p4 * 4]) = v;
    }
    {
        int k = tid >> 2, n4 = tid & 3;
        float4 vb = *reinterpret_cast<const float4*>(
            g_proj + (size_t)(t0 + k) * PROJ + OFF_B + h * DSTATE + n4 * 4);
        float4 vc = *reinterpret_cast<const float4*>(
            g_proj + (size_t)(t0 + k) * PROJ + OFF_C + h * DSTATE + n4 * 4);
        *reinterpret_cast<float4*>(&Bsh[k][n4 * 4]) = vb;
        *reinterpret_cast<float4*>(&Csh[k][n4 * 4]) = vc;
    }
    if (tid < 64) {
        const float* row = g_proj + (size_t)(t0 + tid) * PROJ + OFF_DT;
        float acc = dt_b[h];
#pragma unroll
        for (int r = 0; r < DTRANK; ++r)
            acc = fmaf(row[r], dt_W[h * DTRANK + r], acc);
        dts[tid] = (acc > 20.f) ? acc : log1pf(expf(acc));
    }
    __syncthreads();

    if (wid == 0) {
        float A  = -expf(A_log[h]);
        float v1 = dts[2 * lid + 1] * A;
        float s  = dts[2 * lid] * A + v1;
#pragma unroll
        for (int off = 1; off < 32; off <<= 1) {
            float t = __shfl_up_sync(0xffffffffu, s, off);
            if (lid >= off) s += t;
        }
        dacs[2 * lid + 1] = s;
        dacs[2 * lid]     = s - v1;
    }
    __syncthreads();

    if (tid < 64) {
        wk[tid] = dts[tid] * expf(dacs[63] - dacs[tid]);
        g_dacs[(size_t)(t0 + tid) * NHEADS + h] = dacs[tid];
    }
    if (tid == 0) g_cdecay[bid] = expf(dacs[63]);
    __syncthreads();

    // scores: thread owns row i = tid&63, columns j0..j0+15; writes transposed.
    // B rows loaded as float4 (4 LDS.128 instead of 16 scalar LDS per j).
    {
        int i  = tid & 63;
        int j0 = (tid >> 6) * 16;
        float ci[16];
#pragma unroll
        for (int n = 0; n < 16; ++n) ci[n] = Csh[i][n];
        float di = dacs[i];
#pragma unroll
        for (int jj = 0; jj < 16; ++jj) {
            int j = j0 + jj;
            float v = 0.f;
            if (j <= i) {
                float d = 0.f;
#pragma unroll
                for (int q = 0; q < 4; ++q) {
                    float4 b4 = *reinterpret_cast<const float4*>(&Bsh[j][q * 4]);
                    d = fmaf(ci[q * 4 + 0], b4.x, d);
                    d = fmaf(ci[q * 4 + 1], b4.y, d);
                    d = fmaf(ci[q * 4 + 2], b4.z, d);
                    d = fmaf(ci[q * 4 + 3], b4.w, d);
                }
                v = d * expf(di - dacs[j]) * dts[j];
            }
            scT[j][i] = v;
        }
    }
    __syncthreads();

    // bw[k][n] = B[k][n] * wk[k]  (overwrite Csh, dead after scores)
    for (int idx = tid; idx < 64 * 16; idx += 256) {
        int k = idx >> 4, n = idx & 15;
        Csh[k][n] = Bsh[k][n] * wk[k];
    }
    __syncthreads();

    // y_intra: 4x4 register blocking, causal-truncated k loop, float4 LDS both
    {
        int a  = tid >> 4;
        int b  = tid & 15;
        int i0 = a * 4, p0 = b * 4;
        float acc[4][4];
#pragma unroll
        for (int q = 0; q < 4; ++q)
#pragma unroll
            for (int r = 0; r < 4; ++r) acc[q][r] = 0.f;
        const int kmax = i0 + 4;          // scT[k][i] = 0 for k > i
        for (int kk = 0; kk < kmax; ++kk) {
            float4 s4 = *reinterpret_cast<const float4*>(&scT[kk][i0]);
            float4 xr = *reinterpret_cast<const float4*>(&xs[kk][p0]);
            acc[0][0] = fmaf(s4.x, xr.x, acc[0][0]);
            acc[0][1] = fmaf(s4.x, xr.y, acc[0][1]);
            acc[0][2] = fmaf(s4.x, xr.z, acc[0][2]);
            acc[0][3] = fmaf(s4.x, xr.w, acc[0][3]);
            acc[1][0] = fmaf(s4.y, xr.x, acc[1][0]);
            acc[1][1] = fmaf(s4.y, xr.y, acc[1][1]);
            acc[1][2] = fmaf(s4.y, xr.z, acc[1][2]);
            acc[1][3] = fmaf(s4.y, xr.w, acc[1][3]);
            acc[2][0] = fmaf(s4.z, xr.x, acc[2][0]);
            acc[2][1] = fmaf(s4.z, xr.y, acc[2][1]);
            acc[2][2] = fmaf(s4.z, xr.z, acc[2][2]);
            acc[2][3] = fmaf(s4.z, xr.w, acc[2][3]);
            acc[3][0] = fmaf(s4.w, xr.x, acc[3][0]);
            acc[3][1] = fmaf(s4.w, xr.y, acc[3][1]);
            acc[3][2] = fmaf(s4.w, xr.z, acc[3][2]);
            acc[3][3] = fmaf(s4.w, xr.w, acc[3][3]);
        }
#pragma unroll
        for (int q = 0; q < 4; ++q) {
            float4 v = make_float4(acc[q][0], acc[q][1], acc[q][2], acc[q][3]);
            *reinterpret_cast<float4*>(
                g_y + (size_t)(t0 + i0 + q) * DINNER + h * HDIM + p0) = v;
        }
    }

    // chunk_state[n][p] = sum_k bw[k][n] * x[k][p]
    {
        int n  = tid >> 4;
        int p0 = (tid & 15) * 4;
        float4 acc = make_float4(0.f, 0.f, 0.f, 0.f);
        for (int k = 0; k < 64; ++k) {
            float bwv = Csh[k][n];
            float4 xr = *reinterpret_cast<const float4*>(&xs[k][p0]);
            acc.x = fmaf(bwv, xr.x, acc.x);
            acc.y = fmaf(bwv, xr.y, acc.y);
            acc.z = fmaf(bwv, xr.z, acc.z);
            acc.w = fmaf(bwv, xr.w, acc.w);
        }
        *reinterpret_cast<float4*>(
            g_cs + (size_t)bid * (DSTATE * HDIM) + n * HDIM + p0) = acc;
    }
}

// ---------------------------------------------------------------------------
// Sequential scan over chunks: grid = BATCH*NHEADS*4, 1 elem/thread
// ---------------------------------------------------------------------------
__global__ void __launch_bounds__(256)
scan_kernel()
{
    const int g   = blockIdx.x;
    const int bh  = g >> 2;
    const int seg = g & 3;
    const int b   = bh >> 4;
    const int h   = bh & 15;
    const int e   = seg * 256 + threadIdx.x;

    const int    chid0  = (b * NCHUNK) * NHEADS + h;
    const size_t base   = (size_t)chid0 * (DSTATE * HDIM);
    const size_t stride = (size_t)NHEADS * DSTATE * HDIM;

    float hv  = 0.f;
    float cur = g_cs[base + e];
    float d   = g_cdecay[chid0];
    for (int c = 0; c < NCHUNK; ++c) {
        float nxt = 0.f, dn = 0.f;
        if (c + 1 < NCHUNK) {
            nxt = g_cs[base + stride * (c + 1) + e];
            dn  = g_cdecay[chid0 + (c + 1) * NHEADS];
        }
        g_hs[base + stride * c + e] = hv;
        hv = fmaf(d, hv, cur);
        cur = nxt; d = dn;
    }
}

// ---------------------------------------------------------------------------
// Cross-chunk + skip (hs rows loaded as float4)
// ---------------------------------------------------------------------------
__global__ void __launch_bounds__(256, 2)
cross_kernel(const float* __restrict__ D_param)
{
    const int bid = blockIdx.x;
    const int h   = bid & 15;
    const int bc  = bid >> 4;
    const int t0  = bc * CHUNK;
    const int tid = threadIdx.x;

    __shared__ float hs[16][68];
    __shared__ float Csh[64][20];
    __shared__ float dacs[64];

    {
        int n = tid >> 4, pg = tid & 15;
        float4 v = *reinterpret_cast<const float4*>(
            g_hs + (size_t)bid * (DSTATE * HDIM) + n * HDIM + pg * 4);
        *reinterpret_cast<float4*>(&hs[n][pg * 4]) = v;
    }
    {
        int k = tid >> 2, n4 = tid & 3;
        float4 vc = *reinterpret_cast<const float4*>(
            g_proj + (size_t)(t0 + k) * PROJ + OFF_C + h * DSTATE + n4 * 4);
        *reinterpret_cast<float4*>(&Csh[k][n4 * 4]) = vc;
    }
    if (tid < 64) dacs[tid] = g_dacs[(size_t)(t0 + tid) * NHEADS + h];
    __syncthreads();

    int i  = tid >> 2;
    int p0 = (tid & 3) * 16;
    float ci[16];
#pragma unroll
    for (int n = 0; n < 16; ++n) ci[n] = Csh[i][n];
    float e  = expf(dacs[i]);
    float dp = D_param[h];

    size_t t = (size_t)(t0 + i);
    const float* xrow = g_proj + t * PROJ + OFF_XP + h * HDIM;
    float* yrow = g_y + t * DINNER + h * HDIM;
#pragma unroll
    for (int g4 = 0; g4 < 4; ++g4) {
        int p = p0 + g4 * 4;
        float4 yv = *reinterpret_cast<const float4*>(yrow + p);
        float4 xv = *reinterpret_cast<const float4*>(xrow + p);
        float a0 = 0.f, a1 = 0.f, a2 = 0.f, a3 = 0.f;
#pragma unroll
        for (int n = 0; n < 16; ++n) {
            float c = ci[n];
            float4 h4 = *reinterpret_cast<const float4*>(&hs[n][p]);
            a0 = fmaf(c, h4.x, a0);
            a1 = fmaf(c, h4.y, a1);
            a2 = fmaf(c, h4.z, a2);
            a3 = fmaf(c, h4.w, a3);
        }
        float4 o;
        o.x = yv.x + e * a0 + dp * xv.x;
        o.y = yv.y + e * a1 + dp * xv.y;
        o.z = yv.z + e * a2 + dp * xv.z;
        o.w = yv.w + e * a3 + dp * xv.w;
        *reinterpret_cast<float4*>(yrow + p) = o;
    }
}

// ---------------------------------------------------------------------------
// RMS norm + SiLU gate -> yg packed (bf16 hi/lo, swizzled A-tile layout)
// ---------------------------------------------------------------------------
__global__ void __launch_bounds__(256)
norm_kernel(const float* __restrict__ norm_w)
{
    const int t   = blockIdx.x;
    const int tid = threadIdx.x;

    float4 v = reinterpret_cast<const float4*>(g_y + (size_t)t * DINNER)[tid];
    float ss = v.x * v.x + v.y * v.y + v.z * v.z + v.w * v.w;
#pragma unroll
    for (int off = 16; off > 0; off >>= 1)
        ss += __shfl_xor_sync(0xffffffffu, ss, off);

    __shared__ float red[8];
    __shared__ float s_inv;
    if ((tid & 31) == 0) red[tid >> 5] = ss;
    __syncthreads();
    if (tid == 0) {
        float s = 0.f;
#pragma unroll
        for (int i = 0; i < 8; ++i) s += red[i];
        s_inv = rsqrtf(s * (1.f / DINNER) + 1e-6f);
    }
    __syncthreads();
    float inv = s_inv;

    const float* zrow = g_proj + (size_t)t * PROJ + OFF_Z;
    int c = tid * 4;
    float4 z4 = *reinterpret_cast<const float4*>(zrow + c);
    float4 w4 = *reinterpret_cast<const float4*>(norm_w + c);
    float4 o;
    o.x = v.x * inv * w4.x * (z4.x / (1.f + expf(-z4.x)));
    o.y = v.y * inv * w4.y * (z4.y / (1.f + expf(-z4.y)));
    o.z = v.z * inv * w4.z * (z4.z / (1.f + expf(-z4.z)));
    o.w = v.w * inv * w4.w * (z4.w / (1.f + expf(-z4.w)));

    uint2 h, l;
    split4(o, h, l);
    size_t  blk = APK_BLK(t >> 8, c >> 6);
    uint32_t off = (uint32_t)((t & 255) * 128 + (c & 63) * 2);
    off = SW128(off);
    *reinterpret_cast<uint2*>(g_yghi + blk + off) = h;
    *reinterpret_cast<uint2*>(g_yglo + blk + off) = l;
}

// ---------------------------------------------------------------------------
// Launch — proj GEMM at slot #4 (profiled)
// ---------------------------------------------------------------------------
extern "C" void kernel_launch(void* const* d_in, const int* in_sizes, int n_in,
                              void* d_out, int out_size)
{
    const float* x      = (const float*)d_in[0];
    const float* W_in   = (const float*)d_in[1];
    const float* dt_W   = (const float*)d_in[2];
    const float* dt_b   = (const float*)d_in[3];
    const float* A_log  = (const float*)d_in[4];
    const float* D_par  = (const float*)d_in[5];
    const float* W_out  = (const float*)d_in[6];
    const float* norm_w = (const float*)d_in[7];
    float* out = (float*)d_out;

    float* proj_ptr = nullptr;
    uint8_t *xhi, *xlo, *winhi, *winlo, *wouthi, *woutlo, *yghi, *yglo;
    cudaGetSymbolAddress((void**)&proj_ptr, g_proj);
    cudaGetSymbolAddress((void**)&xhi, g_xhi);
    cudaGetSymbolAddress((void**)&xlo, g_xlo);
    cudaGetSymbolAddress((void**)&winhi, g_winhi);
    cudaGetSymbolAddress((void**)&winlo, g_winlo);
    cudaGetSymbolAddress((void**)&wouthi, g_wouthi);
    cudaGetSymbolAddress((void**)&woutlo, g_woutlo);
    cudaGetSymbolAddress((void**)&yghi, g_yghi);
    cudaGetSymbolAddress((void**)&yglo, g_yglo);

    cudaFuncSetAttribute(gemm_tc, cudaFuncAttributeMaxDynamicSharedMemorySize, GEMM_SMEM_BYTES);

    // 1) pack x
    {
        int n4 = TOKENS * DMODEL / 4;
        split_pack_A<<<(n4 + 255) / 256, 256>>>(x, xhi, xlo, n4);
    }
    // 2) pack W_in (padded to 2688 rows)
    {
        int n4 = PROJPAD * DMODEL / 4;
        split_pack_B<<<(n4 + 255) / 256, 256>>>(W_in, winhi, winlo, PROJ, n4);
    }
    // 3) pack W_out
    {
        int n4 = DMODEL * DINNER / 4;
        split_pack_B<<<(n4 + 255) / 256, 256>>>(W_out, wouthi, woutlo, DMODEL, n4);
    }
    // 4) proj = x @ W_in^T   [16384, 2576]   <- profiled slot
    {
        dim3 grid(PROJPAD / 128, TOKENS / 256);
        gemm_tc<<<grid, 256, GEMM_SMEM_BYTES>>>(xhi, xlo, winhi, winlo,
                                                proj_ptr, DMODEL / 64, PROJ, PROJ);
    }
    // 5) intra-chunk (+dt)
    intra_kernel<<<BATCH * NCHUNK * NHEADS, 256>>>(dt_W, dt_b, A_log);
    // 6) chunk scan
    scan_kernel<<<BATCH * NHEADS * 4, 256>>>();
    // 7) cross-chunk + skip
    cross_kernel<<<BATCH * NCHUNK * NHEADS, 256>>>(D_par);
    // 8) RMS norm + gate -> packed bf16 hi/lo
    norm_kernel<<<TOKENS, 256>>>(norm_w);
    // 9) out = yg @ W_out^T  [16384, 1024]
    {
        dim3 grid(DMODEL / 128, TOKENS / 256);
        gemm_tc<<<grid, 256, GEMM_SMEM_BYTES>>>(yghi, yglo, wouthi, woutlo,
                                                out, DINNER / 64, DMODEL, DMODEL);
    }
}

// round 15
// speedup vs baseline: 1.0793x; 1.0307x over previous
#include <cuda_runtime.h>
#include <cuda_bf16.h>
#include <cstdint>

// ---------------------------------------------------------------------------
// Problem constants
// ---------------------------------------------------------------------------
#define BATCH   4
#define SEQ     4096
#define TOKENS  (BATCH * SEQ)        // 16384
#define DMODEL  1024
#define DINNER  1024
#define NHEADS  16
#define HDIM    64
#define DSTATE  16
#define DTRANK  16
#define CHUNK   64
#define NCHUNK  (SEQ / CHUNK)        // 64
#define PROJ    2576
#define PROJPAD 2688                 // 21 * 128

#define OFF_XP   0
#define OFF_Z    1024
#define OFF_B    2048
#define OFF_C    2304
#define OFF_DT   2560

// Packed-operand block offsets (bytes). A-pack: 256-row tiles; B-pack: 128-row.
// Both GEMMs have K=1024 -> exactly 16 chunks of 64 columns.
#define APK_BLK(mt, ch) ((((size_t)(mt) * 16) + (size_t)(ch)) * 32768)
#define BPK_BLK(nt, ch) ((((size_t)(nt) * 16) + (size_t)(ch)) * 16384)
#define SW128(o) ((o) ^ (((o) >> 3) & 0x70))

// tcgen05 is an arch-SPECIFIC feature: only emit it in the sm_103a/f passes.
#if defined(__CUDA_ARCH_FEAT_SM103_ALL) || \
    (defined(__CUDA_ARCH_FAMILY_SPECIFIC__) && __CUDA_ARCH_FAMILY_SPECIFIC__ >= 1000) || \
    (defined(__CUDA_ARCH_SPECIFIC__) && __CUDA_ARCH_SPECIFIC__ >= 1000)
#define HAS_TCGEN05 1
#else
#define HAS_TCGEN05 0
#endif

// ---------------------------------------------------------------------------
// PTX helpers (guarded)
// ---------------------------------------------------------------------------
#if HAS_TCGEN05
__device__ __forceinline__ uint32_t smem_to_u32(const void* p) {
    uint32_t a;
    asm("{ .reg .u64 t; cvta.to.shared.u64 t, %1; cvt.u32.u64 %0, t; }" : "=r"(a) : "l"(p));
    return a;
}
__device__ __forceinline__ uint32_t elect_one_pred() {
    uint32_t pred;
    asm volatile("{\n\t.reg .pred p;\n\telect.sync _|p, 0xFFFFFFFF;\n\tselp.b32 %0, 1, 0, p;\n\t}" : "=r"(pred));
    return pred;
}
#define TCGEN05_ALLOC(smem_result_addr, nCols) \
    asm volatile("tcgen05.alloc.cta_group::1.sync.aligned.shared::cta.b32 [%0], %1;" \
        :: "r"((uint32_t)(smem_result_addr)), "r"((uint32_t)(nCols)) : "memory")
#define TCGEN05_DEALLOC(tmem_addr, nCols) \
    asm volatile("tcgen05.dealloc.cta_group::1.sync.aligned.b32 %0, %1;" :: "r"(tmem_addr), "r"((uint32_t)(nCols)))
#define TCGEN05_RELINQUISH() \
    asm volatile("tcgen05.relinquish_alloc_permit.cta_group::1.sync.aligned;")
#define TCGEN05_COMMIT(mbar) \
    asm volatile("tcgen05.commit.cta_group::1.mbarrier::arrive::one.shared::cluster.b64 [%0];" \
        :: "r"((uint32_t)(mbar)) : "memory")
#define TCGEN05_FENCE_AFTER()  asm volatile("tcgen05.fence::after_thread_sync;" ::: "memory")
#define TCGEN05_FENCE_BEFORE() asm volatile("tcgen05.fence::before_thread_sync;" ::: "memory")
#define TCGEN05_WAIT_LD()      asm volatile("tcgen05.wait::ld.sync.aligned;" ::: "memory")
#define MBARRIER_INIT(mbar, count) \
    asm volatile("mbarrier.init.shared.b64 [%0], %1;" :: "r"((uint32_t)(mbar)), "r"((uint32_t)(count)) : "memory")
#define FENCE_PROXY_ASYNC() asm volatile("fence.proxy.async.shared::cta;" ::: "memory")
#define CP_ASYNC16(dst, src) \
    asm volatile("cp.async.cg.shared.global [%0], [%1], 16;" \
        :: "r"((uint32_t)(dst)), "l"(src) : "memory")
#define CP_ASYNC_COMMIT() asm volatile("cp.async.commit_group;" ::: "memory")
#define CP_ASYNC_WAIT0()  asm volatile("cp.async.wait_group 0;" ::: "memory")
#define MBARRIER_WAIT_PARITY(mbar, parity) do { \
    uint32_t _m = (uint32_t)(mbar); uint32_t _p = (uint32_t)(parity); uint32_t _d; \
    asm volatile("{\n\t.reg .pred p;\n\t" \
        "mbarrier.try_wait.parity.acquire.cta.shared::cta.b64 p, [%1], %2;\n\t" \
        "selp.b32 %0, 1, 0, p;\n\t}" : "=r"(_d) : "r"(_m), "r"(_p) : "memory"); \
    if (!_d) { \
        asm volatile("{\n\t.reg .pred P1;\n\t" \
            "WL_%=:\n\t" \
            "mbarrier.try_wait.parity.acquire.cta.shared::cta.b64 P1, [%0], %1, 0x989680;\n\t" \
            "@P1 bra.uni WD_%=;\n\t" \
            "bra.uni WL_%=;\n\t" \
            "WD_%=:\n\t}" :: "r"(_m), "r"(_p) : "memory"); \
    } } while (0)
#define TCGEN05_LD_32X32B_X32(r, tmem_addr) \
    asm volatile("tcgen05.ld.sync.aligned.32x32b.x32.b32 " \
        "{%0, %1, %2, %3, %4, %5, %6, %7, %8, %9, %10, %11, %12, %13, %14, %15, " \
        " %16, %17, %18, %19, %20, %21, %22, %23, %24, %25, %26, %27, %28, %29, %30, %31}, [%32];" \
        : "=r"((r)[0]),  "=r"((r)[1]),  "=r"((r)[2]),  "=r"((r)[3]), \
          "=r"((r)[4]),  "=r"((r)[5]),  "=r"((r)[6]),  "=r"((r)[7]), \
          "=r"((r)[8]),  "=r"((r)[9]),  "=r"((r)[10]), "=r"((r)[11]), \
          "=r"((r)[12]), "=r"((r)[13]), "=r"((r)[14]), "=r"((r)[15]), \
          "=r"((r)[16]), "=r"((r)[17]), "=r"((r)[18]), "=r"((r)[19]), \
          "=r"((r)[20]), "=r"((r)[21]), "=r"((r)[22]), "=r"((r)[23]), \
          "=r"((r)[24]), "=r"((r)[25]), "=r"((r)[26]), "=r"((r)[27]), \
          "=r"((r)[28]), "=r"((r)[29]), "=r"((r)[30]), "=r"((r)[31]) \
        : "r"(tmem_addr))

static constexpr uint64_t SMEM_DESC_BASE_SW128 =
    (uint64_t(2) << 61) | (uint64_t(1) << 46) | (uint64_t(64) << 32) | (uint64_t(1) << 16);
#define MAKE_SMEM_DESC(base_addr) (SMEM_DESC_BASE_SW128 | ((uint64_t)((base_addr) >> 4) & 0x3FFF))

// idesc: dtype=F32(bit4), atype=BF16(bit7), btype=BF16(bit10), N/8 @17, M/16 @24
#define MMA_IDESC_128x128 ((1u << 4) | (1u << 7) | (1u << 10) | (16u << 17) | (8u << 24))

__device__ __forceinline__ void mma_f16_ss(uint32_t d_tmem, uint64_t a_desc, uint64_t b_desc,
                                           uint32_t idesc, uint32_t enable)
{
    asm volatile(
        "{\n\t.reg .pred p;\n\t"
        "setp.ne.u32 p, %4, 0;\n\t"
        "tcgen05.mma.cta_group::1.kind::f16 [%0], %1, %2, %3, {%5, %5, %5, %5}, p;\n\t"
        "}"
        :: "r"(d_tmem), "l"(a_desc), "l"(b_desc), "r"(idesc), "r"(enable), "r"(0u)
        : "memory");
}
#endif  // HAS_TCGEN05

// ---------------------------------------------------------------------------
// Scratch (device globals; no allocation allowed)
// ---------------------------------------------------------------------------
__device__ float g_proj[(size_t)TOKENS * PROJ];
__device__ float g_dacs[(size_t)TOKENS * NHEADS];
__device__ float g_y[(size_t)TOKENS * DINNER];
__device__ float g_cs[(size_t)BATCH * NCHUNK * NHEADS * DSTATE * HDIM];
__device__ float g_hs[(size_t)BATCH * NCHUNK * NHEADS * DSTATE * HDIM];
__device__ float g_cdecay[(size_t)BATCH * NCHUNK * NHEADS];

__device__ __align__(1024) uint8_t g_xhi[(size_t)TOKENS * DMODEL * 2];
__device__ __align__(1024) uint8_t g_xlo[(size_t)TOKENS * DMODEL * 2];
__device__ __align__(1024) uint8_t g_winhi[(size_t)PROJPAD * DMODEL * 2];
__device__ __align__(1024) uint8_t g_winlo[(size_t)PROJPAD * DMODEL * 2];
__device__ __align__(1024) uint8_t g_wouthi[(size_t)DMODEL * DINNER * 2];
__device__ __align__(1024) uint8_t g_woutlo[(size_t)DMODEL * DINNER * 2];
__device__ __align__(1024) uint8_t g_yghi[(size_t)TOKENS * DINNER * 2];
__device__ __align__(1024) uint8_t g_yglo[(size_t)TOKENS * DINNER * 2];

// ---------------------------------------------------------------------------
// hi/lo split helper
// ---------------------------------------------------------------------------
__device__ __forceinline__ void split4(float4 v, uint2& h, uint2& l)
{
    __nv_bfloat16 hx = __float2bfloat16(v.x), hy = __float2bfloat16(v.y);
    __nv_bfloat16 hz = __float2bfloat16(v.z), hw = __float2bfloat16(v.w);
    __nv_bfloat162 h01 = {hx, hy}, h23 = {hz, hw};
    __nv_bfloat162 l01 = {__float2bfloat16(v.x - __bfloat162float(hx)),
                          __float2bfloat16(v.y - __bfloat162float(hy))};
    __nv_bfloat162 l23 = {__float2bfloat16(v.z - __bfloat162float(hz)),
                          __float2bfloat16(v.w - __bfloat162float(hw))};
    h.x = *reinterpret_cast<uint32_t*>(&h01);
    h.y = *reinterpret_cast<uint32_t*>(&h23);
    l.x = *reinterpret_cast<uint32_t*>(&l01);
    l.y = *reinterpret_cast<uint32_t*>(&l23);
}

// Pack activations (256-row A tiles): src [rows][1024] fp32 -> swizzled blocks
__global__ void __launch_bounds__(256)
split_pack_A(const float* __restrict__ src, uint8_t* __restrict__ hi,
             uint8_t* __restrict__ lo, int n4)
{
    int i = blockIdx.x * 256 + threadIdx.x;
    if (i >= n4) return;
    int t  = i >> 8;
    int k0 = (i & 255) * 4;
    float4 v = reinterpret_cast<const float4*>(src)[i];
    uint2 h, l;
    split4(v, h, l);
    size_t  blk = APK_BLK(t >> 8, k0 >> 6);
    uint32_t off = (uint32_t)((t & 255) * 128 + (k0 & 63) * 2);
    off = SW128(off);
    *reinterpret_cast<uint2*>(hi + blk + off) = h;
    *reinterpret_cast<uint2*>(lo + blk + off) = l;
}

// Pack weights (128-row B tiles) with zero row padding
__global__ void __launch_bounds__(256)
split_pack_B(const float* __restrict__ src, uint8_t* __restrict__ hi,
             uint8_t* __restrict__ lo, int rows_src, int n4)
{
    int i = blockIdx.x * 256 + threadIdx.x;
    if (i >= n4) return;
    int r  = i >> 8;
    int k0 = (i & 255) * 4;
    float4 v = make_float4(0.f, 0.f, 0.f, 0.f);
    if (r < rows_src) v = reinterpret_cast<const float4*>(src)[i];
    uint2 h, l;
    split4(v, h, l);
    size_t  blk = BPK_BLK(r >> 7, k0 >> 6);
    uint32_t off = (uint32_t)((r & 127) * 128 + (k0 & 63) * 2);
    off = SW128(off);
    *reinterpret_cast<uint2*>(hi + blk + off) = h;
    *reinterpret_cast<uint2*>(lo + blk + off) = l;
}

// ---------------------------------------------------------------------------
// tcgen05 bf16-split GEMM, packed operands, cp.async staging.
// SINGLE 96KB stage + 2 CTAs/SM: the two resident CTAs anti-phase, so one
// CTA's MMA (1536 cyc) overlaps the other's copy stream. Per-CTA loop:
//   wait done(c-1) -> copy(c) -> wait_group 0 -> sync -> MMA(c) -> commit.
// Every thread walks every done phase in order (one final drain for NC-1).
// 256x128 tile, K-chunks of 64. 256 threads, SMEM ~100KB (fits 2/SM).
// Stage layout: Ahi @0 (32K), Alo @32768, Bhi @65536 (16K), Blo @81920.
// ---------------------------------------------------------------------------
#define STAGE_BYTES 98304
#define GEMM_SMEM_BYTES (2048 + STAGE_BYTES)

#if HAS_TCGEN05
__device__ __forceinline__ void gemm_copy_chunk(
    uint32_t stage, int tid,
    const uint8_t* __restrict__ Ahi, const uint8_t* __restrict__ Alo,
    const uint8_t* __restrict__ Bhi, const uint8_t* __restrict__ Blo,
    int mt, int nt, int c)
{
    const uint8_t* sAh = Ahi + APK_BLK(mt, c);
    const uint8_t* sAl = Alo + APK_BLK(mt, c);
    const uint8_t* sBh = Bhi + BPK_BLK(nt, c);
    const uint8_t* sBl = Blo + BPK_BLK(nt, c);
#pragma unroll
    for (int it = 0; it < 8; ++it) {
        uint32_t b = (uint32_t)(it * 256 + tid) * 16u;   // 0..32767
        CP_ASYNC16(stage + b,          sAh + b);
        CP_ASYNC16(stage + 32768u + b, sAl + b);
    }
#pragma unroll
    for (int it = 0; it < 4; ++it) {
        uint32_t b = (uint32_t)(it * 256 + tid) * 16u;   // 0..16383
        CP_ASYNC16(stage + 65536u + b, sBh + b);
        CP_ASYNC16(stage + 81920u + b, sBl + b);
    }
    CP_ASYNC_COMMIT();
}
#endif

__global__ void __launch_bounds__(256, 2)
gemm_tc(const uint8_t* __restrict__ Ahi, const uint8_t* __restrict__ Alo,
        const uint8_t* __restrict__ Bhi, const uint8_t* __restrict__ Blo,
        float* __restrict__ C, int NC, int Nstride, int Nout)
{
#if HAS_TCGEN05
    extern __shared__ char smem[];
    const uint32_t sbase = smem_to_u32(smem);
    const int tid = threadIdx.x;
    const int wid = tid >> 5;
    const int lid = tid & 31;
    const int bm = blockIdx.y * 256;
    const int bn = blockIdx.x * 128;

    const uint32_t TMEMP = sbase;
    const uint32_t DONE0 = sbase + 8;
    const uint32_t DONE1 = sbase + 16;
    const uint32_t BUF   = (sbase + 32 + 1023) & ~1023u;

    if (wid == 0) {
        TCGEN05_ALLOC(TMEMP, 256);
        TCGEN05_RELINQUISH();
    }
    if (tid == 0) { MBARRIER_INIT(DONE0, 1); MBARRIER_INIT(DONE1, 1); }
    __syncthreads();
    uint32_t tmem;
    asm volatile("ld.shared.b32 %0, [%1];" : "=r"(tmem) : "r"(TMEMP));

    for (int c = 0; c < NC; ++c) {
        // stage reuse: MMA(c-1) must have finished reading it
        if (c >= 1) {
            const uint32_t pdone = ((c - 1) & 1) ? DONE1 : DONE0;
            MBARRIER_WAIT_PARITY(pdone, ((c - 1) >> 1) & 1);
        }
        gemm_copy_chunk(BUF, tid, Ahi, Alo, Bhi, Blo, blockIdx.y, blockIdx.x, c);
        CP_ASYNC_WAIT0();
        __syncthreads();

        if (wid == 0) {
            FENCE_PROXY_ASYNC();
            if (elect_one_pred()) {
                uint64_t dA0h = MAKE_SMEM_DESC(BUF);
                uint64_t dA1h = MAKE_SMEM_DESC(BUF + 16384);
                uint64_t dA0l = MAKE_SMEM_DESC(BUF + 32768);
                uint64_t dA1l = MAKE_SMEM_DESC(BUF + 49152);
                uint64_t dBh  = MAKE_SMEM_DESC(BUF + 65536);
                uint64_t dBl  = MAKE_SMEM_DESC(BUF + 81920);
#pragma unroll
                for (int ks = 0; ks < 4; ++ks) {
                    uint32_t en0 = (c == 0 && ks == 0) ? 0u : 1u;
                    mma_f16_ss(tmem,       dA0h + ks * 2, dBh + ks * 2, MMA_IDESC_128x128, en0);
                    mma_f16_ss(tmem,       dA0h + ks * 2, dBl + ks * 2, MMA_IDESC_128x128, 1u);
                    mma_f16_ss(tmem,       dA0l + ks * 2, dBh + ks * 2, MMA_IDESC_128x128, 1u);
                    mma_f16_ss(tmem + 128, dA1h + ks * 2, dBh + ks * 2, MMA_IDESC_128x128, en0);
                    mma_f16_ss(tmem + 128, dA1h + ks * 2, dBl + ks * 2, MMA_IDESC_128x128, 1u);
                    mma_f16_ss(tmem + 128, dA1l + ks * 2, dBh + ks * 2, MMA_IDESC_128x128, 1u);
                }
                TCGEN05_COMMIT(((c & 1) ? DONE1 : DONE0));
            }
        }
        __syncthreads();   // all threads see the commit before next iteration
    }

    // final drain: done(NC-1); done(NC-2) was walked in iteration NC-1
    MBARRIER_WAIT_PARITY(((NC - 1) & 1) ? DONE1 : DONE0, ((NC - 1) >> 1) & 1);
    TCGEN05_FENCE_AFTER();

    {
        int mt  = wid >> 2;                       // 0 or 1
        int row = bm + mt * 128 + (wid & 3) * 32 + lid;
        float* crow = C + (size_t)row * Nstride + bn;
        uint32_t tcol = tmem + (uint32_t)(mt * 128);
#pragma unroll
        for (int g = 0; g < 4; ++g) {
            uint32_t r[32];
            TCGEN05_LD_32X32B_X32(r, tcol + g * 32);
            TCGEN05_WAIT_LD();
            int n0 = bn + g * 32;
            if (n0 + 32 <= Nout) {
#pragma unroll
                for (int j = 0; j < 32; j += 4) {
                    float4 v = make_float4(__uint_as_float(r[j]), __uint_as_float(r[j + 1]),
                                           __uint_as_float(r[j + 2]), __uint_as_float(r[j + 3]));
                    *reinterpret_cast<float4*>(crow + g * 32 + j) = v;
                }
            } else {
                for (int j = 0; j < 32; ++j)
                    if (n0 + j < Nout) crow[g * 32 + j] = __uint_as_float(r[j]);
            }
        }
        TCGEN05_FENCE_BEFORE();
    }
    __syncthreads();
    if (wid == 0) TCGEN05_DEALLOC(tmem, 256);

#else   // ---------------- SIMT fallback (generic PTX pass only; never runs) --
    const int tid = threadIdx.x;
    const int bm  = blockIdx.y * 256;
    const int bn  = blockIdx.x * 128;
    const int K   = NC * 64;
    for (int e = tid; e < 256 * 128; e += 256) {
        int i = e >> 7, j = e & 127;
        int m = bm + i, n = bn + j;
        if (n >= Nout) continue;
        float acc = 0.f;
        for (int k = 0; k < K; ++k) {
            size_t ablk = APK_BLK(m >> 8, k >> 6);
            uint32_t aoff = SW128((uint32_t)((m & 255) * 128 + (k & 63) * 2));
            size_t bblk = BPK_BLK(n >> 7, k >> 6);
            uint32_t boff = SW128((uint32_t)((n & 127) * 128 + (k & 63) * 2));
            float a = __bfloat162float(*(const __nv_bfloat16*)(Ahi + ablk + aoff)) +
                      __bfloat162float(*(const __nv_bfloat16*)(Alo + ablk + aoff));
            float b = __bfloat162float(*(const __nv_bfloat16*)(Bhi + bblk + boff)) +
                      __bfloat162float(*(const __nv_bfloat16*)(Blo + bblk + boff));
            acc = fmaf(a, b, acc);
        }
        C[(size_t)m * Nstride + n] = acc;
    }
#endif
}

// ---------------------------------------------------------------------------
// Intra-chunk (dt folded in): dt -> dacs -> scores(T) -> y_intra, chunk_state
// ---------------------------------------------------------------------------
__global__ void __launch_bounds__(256, 3)
intra_kernel(const float* __restrict__ dt_W, const float* __restrict__ dt_b,
             const float* __restrict__ A_log)
{
    const int bid = blockIdx.x;        // (b*NCHUNK + c)*NHEADS + h
    const int h   = bid & 15;
    const int bc  = bid >> 4;
    const int t0  = bc * CHUNK;
    const int tid = threadIdx.x;
    const int wid = tid >> 5;
    const int lid = tid & 31;

    __shared__ float xs[64][68];
    __shared__ float scT[64][68];      // scT[k][i] = scores[i][k]
    __shared__ float Bsh[64][20];
    __shared__ float Csh[64][20];      // reused as bw after scores
    __shared__ float dts[64];
    __shared__ float dacs[64];
    __shared__ float wk[64];

    for (int idx = tid; idx < 64 * 16; idx += 256) {
        int k = idx >> 4, p4 = idx & 15;
        float4 v = *reinterpret_cast<const float4*>(
            g_proj + (size_t)(t0 + k) * PROJ + OFF_XP + h * HDIM + p4 * 4);
        *reinterpret_cast<float4*>(&xs[k][p4 * 4]) = v;
    }
    {
        int k = tid >> 2, n4 = tid & 3;
        float4 vb = *reinterpret_cast<const float4*>(
            g_proj + (size_t)(t0 + k) * PROJ + OFF_B + h * DSTATE + n4 * 4);
        float4 vc = *reinterpret_cast<const float4*>(
            g_proj + (size_t)(t0 + k) * PROJ + OFF_C + h * DSTATE + n4 * 4);
        *reinterpret_cast<float4*>(&Bsh[k][n4 * 4]) = vb;
        *reinterpret_cast<float4*>(&Csh[k][n4 * 4]) = vc;
    }
    if (tid < 64) {
        const float* row = g_proj + (size_t)(t0 + tid) * PROJ + OFF_DT;
        float acc = dt_b[h];
#pragma unroll
        for (int r = 0; r < DTRANK; ++r)
            acc = fmaf(row[r], dt_W[h * DTRANK + r], acc);
        dts[tid] = (acc > 20.f) ? acc : log1pf(expf(acc));
    }
    __syncthreads();

    if (wid == 0) {
        float A  = -expf(A_log[h]);
        float v1 = dts[2 * lid + 1] * A;
        float s  = dts[2 * lid] * A + v1;
#pragma unroll
        for (int off = 1; off < 32; off <<= 1) {
            float t = __shfl_up_sync(0xffffffffu, s, off);
            if (lid >= off) s += t;
        }
        dacs[2 * lid + 1] = s;
        dacs[2 * lid]     = s - v1;
    }
    __syncthreads();

    if (tid < 64) {
        wk[tid] = dts[tid] * expf(dacs[63] - dacs[tid]);
        g_dacs[(size_t)(t0 + tid) * NHEADS + h] = dacs[tid];
    }
    if (tid == 0) g_cdecay[bid] = expf(dacs[63]);
    __syncthreads();

    // scores: thread owns row i = tid&63, columns j0..j0+15; writes transposed.
    {
        int i  = tid & 63;
        int j0 = (tid >> 6) * 16;
        float ci[16];
#pragma unroll
        for (int n = 0; n < 16; ++n) ci[n] = Csh[i][n];
        float di = dacs[i];
#pragma unroll
        for (int jj = 0; jj < 16; ++jj) {
            int j = j0 + jj;
            float v = 0.f;
            if (j <= i) {
                float d = 0.f;
#pragma unroll
                for (int q = 0; q < 4; ++q) {
                    float4 b4 = *reinterpret_cast<const float4*>(&Bsh[j][q * 4]);
                    d = fmaf(ci[q * 4 + 0], b4.x, d);
                    d = fmaf(ci[q * 4 + 1], b4.y, d);
                    d = fmaf(ci[q * 4 + 2], b4.z, d);
                    d = fmaf(ci[q * 4 + 3], b4.w, d);
                }
                v = d * expf(di - dacs[j]) * dts[j];
            }
            scT[j][i] = v;
        }
    }
    __syncthreads();

    // bw[k][n] = B[k][n] * wk[k]  (overwrite Csh, dead after scores)
    for (int idx = tid; idx < 64 * 16; idx += 256) {
        int k = idx >> 4, n = idx & 15;
        Csh[k][n] = Bsh[k][n] * wk[k];
    }
    __syncthreads();

    // y_intra: 4x4 register blocking, causal-truncated k loop, float4 LDS both
    {
        int a  = tid >> 4;
        int b  = tid & 15;
        int i0 = a * 4, p0 = b * 4;
        float acc[4][4];
#pragma unroll
        for (int q = 0; q < 4; ++q)
#pragma unroll
            for (int r = 0; r < 4; ++r) acc[q][r] = 0.f;
        const int kmax = i0 + 4;          // scT[k][i] = 0 for k > i
        for (int kk = 0; kk < kmax; ++kk) {
            float4 s4 = *reinterpret_cast<const float4*>(&scT[kk][i0]);
            float4 xr = *reinterpret_cast<const float4*>(&xs[kk][p0]);
            acc[0][0] = fmaf(s4.x, xr.x, acc[0][0]);
            acc[0][1] = fmaf(s4.x, xr.y, acc[0][1]);
            acc[0][2] = fmaf(s4.x, xr.z, acc[0][2]);
            acc[0][3] = fmaf(s4.x, xr.w, acc[0][3]);
            acc[1][0] = fmaf(s4.y, xr.x, acc[1][0]);
            acc[1][1] = fmaf(s4.y, xr.y, acc[1][1]);
            acc[1][2] = fmaf(s4.y, xr.z, acc[1][2]);
            acc[1][3] = fmaf(s4.y, xr.w, acc[1][3]);
            acc[2][0] = fmaf(s4.z, xr.x, acc[2][0]);
            acc[2][1] = fmaf(s4.z, xr.y, acc[2][1]);
            acc[2][2] = fmaf(s4.z, xr.z, acc[2][2]);
            acc[2][3] = fmaf(s4.z, xr.w, acc[2][3]);
            acc[3][0] = fmaf(s4.w, xr.x, acc[3][0]);
            acc[3][1] = fmaf(s4.w, xr.y, acc[3][1]);
            acc[3][2] = fmaf(s4.w, xr.z, acc[3][2]);
            acc[3][3] = fmaf(s4.w, xr.w, acc[3][3]);
        }
#pragma unroll
        for (int q = 0; q < 4; ++q) {
            float4 v = make_float4(acc[q][0], acc[q][1], acc[q][2], acc[q][3]);
            *reinterpret_cast<float4*>(
                g_y + (size_t)(t0 + i0 + q) * DINNER + h * HDIM + p0) = v;
        }
    }

    // chunk_state[n][p] = sum_k bw[k][n] * x[k][p]
    {
        int n  = tid >> 4;
        int p0 = (tid & 15) * 4;
        float4 acc = make_float4(0.f, 0.f, 0.f, 0.f);
        for (int k = 0; k < 64; ++k) {
            float bwv = Csh[k][n];
            float4 xr = *reinterpret_cast<const float4*>(&xs[k][p0]);
            acc.x = fmaf(bwv, xr.x, acc.x);
            acc.y = fmaf(bwv, xr.y, acc.y);
            acc.z = fmaf(bwv, xr.z, acc.z);
            acc.w = fmaf(bwv, xr.w, acc.w);
        }
        *reinterpret_cast<float4*>(
            g_cs + (size_t)bid * (DSTATE * HDIM) + n * HDIM + p0) = acc;
    }
}

// ---------------------------------------------------------------------------
// Sequential scan over chunks: grid = BATCH*NHEADS*4, 1 elem/thread
// ---------------------------------------------------------------------------
__global__ void __launch_bounds__(256)
scan_kernel()
{
    const int g   = blockIdx.x;
    const int bh  = g >> 2;
    const int seg = g & 3;
    const int b   = bh >> 4;
    const int h   = bh & 15;
    const int e   = seg * 256 + threadIdx.x;

    const int    chid0  = (b * NCHUNK) * NHEADS + h;
    const size_t base   = (size_t)chid0 * (DSTATE * HDIM);
    const size_t stride = (size_t)NHEADS * DSTATE * HDIM;

    float hv  = 0.f;
    float cur = g_cs[base + e];
    float d   = g_cdecay[chid0];
    for (int c = 0; c < NCHUNK; ++c) {
        float nxt = 0.f, dn = 0.f;
        if (c + 1 < NCHUNK) {
            nxt = g_cs[base + stride * (c + 1) + e];
            dn  = g_cdecay[chid0 + (c + 1) * NHEADS];
        }
        g_hs[base + stride * c + e] = hv;
        hv = fmaf(d, hv, cur);
        cur = nxt; d = dn;
    }
}

// ---------------------------------------------------------------------------
// Cross-chunk + skip (hs rows loaded as float4)
// ---------------------------------------------------------------------------
__global__ void __launch_bounds__(256, 2)
cross_kernel(const float* __restrict__ D_param)
{
    const int bid = blockIdx.x;
    const int h   = bid & 15;
    const int bc  = bid >> 4;
    const int t0  = bc * CHUNK;
    const int tid = threadIdx.x;

    __shared__ float hs[16][68];
    __shared__ float Csh[64][20];
    __shared__ float dacs[64];

    {
        int n = tid >> 4, pg = tid & 15;
        float4 v = *reinterpret_cast<const float4*>(
            g_hs + (size_t)bid * (DSTATE * HDIM) + n * HDIM + pg * 4);
        *reinterpret_cast<float4*>(&hs[n][pg * 4]) = v;
    }
    {
        int k = tid >> 2, n4 = tid & 3;
        float4 vc = *reinterpret_cast<const float4*>(
            g_proj + (size_t)(t0 + k) * PROJ + OFF_C + h * DSTATE + n4 * 4);
        *reinterpret_cast<float4*>(&Csh[k][n4 * 4]) = vc;
    }
    if (tid < 64) dacs[tid] = g_dacs[(size_t)(t0 + tid) * NHEADS + h];
    __syncthreads();

    int i  = tid >> 2;
    int p0 = (tid & 3) * 16;
    float ci[16];
#pragma unroll
    for (int n = 0; n < 16; ++n) ci[n] = Csh[i][n];
    float e  = expf(dacs[i]);
    float dp = D_param[h];

    size_t t = (size_t)(t0 + i);
    const float* xrow = g_proj + t * PROJ + OFF_XP + h * HDIM;
    float* yrow = g_y + t * DINNER + h * HDIM;
#pragma unroll
    for (int g4 = 0; g4 < 4; ++g4) {
        int p = p0 + g4 * 4;
        float4 yv = *reinterpret_cast<const float4*>(yrow + p);
        float4 xv = *reinterpret_cast<const float4*>(xrow + p);
        float a0 = 0.f, a1 = 0.f, a2 = 0.f, a3 = 0.f;
#pragma unroll
        for (int n = 0; n < 16; ++n) {
            float c = ci[n];
            float4 h4 = *reinterpret_cast<const float4*>(&hs[n][p]);
            a0 = fmaf(c, h4.x, a0);
            a1 = fmaf(c, h4.y, a1);
            a2 = fmaf(c, h4.z, a2);
            a3 = fmaf(c, h4.w, a3);
        }
        float4 o;
        o.x = yv.x + e * a0 + dp * xv.x;
        o.y = yv.y + e * a1 + dp * xv.y;
        o.z = yv.z + e * a2 + dp * xv.z;
        o.w = yv.w + e * a3 + dp * xv.w;
        *reinterpret_cast<float4*>(yrow + p) = o;
    }
}

// ---------------------------------------------------------------------------
// RMS norm + SiLU gate -> yg packed (bf16 hi/lo, swizzled A-tile layout)
// ---------------------------------------------------------------------------
__global__ void __launch_bounds__(256)
norm_kernel(const float* __restrict__ norm_w)
{
    const int t   = blockIdx.x;
    const int tid = threadIdx.x;

    float4 v = reinterpret_cast<const float4*>(g_y + (size_t)t * DINNER)[tid];
    float ss = v.x * v.x + v.y * v.y + v.z * v.z + v.w * v.w;
#pragma unroll
    for (int off = 16; off > 0; off >>= 1)
        ss += __shfl_xor_sync(0xffffffffu, ss, off);

    __shared__ float red[8];
    __shared__ float s_inv;
    if ((tid & 31) == 0) red[tid >> 5] = ss;
    __syncthreads();
    if (tid == 0) {
        float s = 0.f;
#pragma unroll
        for (int i = 0; i < 8; ++i) s += red[i];
        s_inv = rsqrtf(s * (1.f / DINNER) + 1e-6f);
    }
    __syncthreads();
    float inv = s_inv;

    const float* zrow = g_proj + (size_t)t * PROJ + OFF_Z;
    int c = tid * 4;
    float4 z4 = *reinterpret_cast<const float4*>(zrow + c);
    float4 w4 = *reinterpret_cast<const float4*>(norm_w + c);
    float4 o;
    o.x = v.x * inv * w4.x * (z4.x / (1.f + expf(-z4.x)));
    o.y = v.y * inv * w4.y * (z4.y / (1.f + expf(-z4.y)));
    o.z = v.z * inv * w4.z * (z4.z / (1.f + expf(-z4.z)));
    o.w = v.w * inv * w4.w * (z4.w / (1.f + expf(-z4.w)));

    uint2 h, l;
    split4(o, h, l);
    size_t  blk = APK_BLK(t >> 8, c >> 6);
    uint32_t off = (uint32_t)((t & 255) * 128 + (c & 63) * 2);
    off = SW128(off);
    *reinterpret_cast<uint2*>(g_yghi + blk + off) = h;
    *reinterpret_cast<uint2*>(g_yglo + blk + off) = l;
}

// ---------------------------------------------------------------------------
// Launch — proj GEMM at slot #4 (profiled)
// ---------------------------------------------------------------------------
extern "C" void kernel_launch(void* const* d_in, const int* in_sizes, int n_in,
                              void* d_out, int out_size)
{
    const float* x      = (const float*)d_in[0];
    const float* W_in   = (const float*)d_in[1];
    const float* dt_W   = (const float*)d_in[2];
    const float* dt_b   = (const float*)d_in[3];
    const float* A_log  = (const float*)d_in[4];
    const float* D_par  = (const float*)d_in[5];
    const float* W_out  = (const float*)d_in[6];
    const float* norm_w = (const float*)d_in[7];
    float* out = (float*)d_out;

    float* proj_ptr = nullptr;
    uint8_t *xhi, *xlo, *winhi, *winlo, *wouthi, *woutlo, *yghi, *yglo;
    cudaGetSymbolAddress((void**)&proj_ptr, g_proj);
    cudaGetSymbolAddress((void**)&xhi, g_xhi);
    cudaGetSymbolAddress((void**)&xlo, g_xlo);
    cudaGetSymbolAddress((void**)&winhi, g_winhi);
    cudaGetSymbolAddress((void**)&winlo, g_winlo);
    cudaGetSymbolAddress((void**)&wouthi, g_wouthi);
    cudaGetSymbolAddress((void**)&woutlo, g_woutlo);
    cudaGetSymbolAddress((void**)&yghi, g_yghi);
    cudaGetSymbolAddress((void**)&yglo, g_yglo);

    cudaFuncSetAttribute(gemm_tc, cudaFuncAttributeMaxDynamicSharedMemorySize, GEMM_SMEM_BYTES);

    // 1) pack x
    {
        int n4 = TOKENS * DMODEL / 4;
        split_pack_A<<<(n4 + 255) / 256, 256>>>(x, xhi, xlo, n4);
    }
    // 2) pack W_in (padded to 2688 rows)
    {
        int n4 = PROJPAD * DMODEL / 4;
        split_pack_B<<<(n4 + 255) / 256, 256>>>(W_in, winhi, winlo, PROJ, n4);
    }
    // 3) pack W_out
    {
        int n4 = DMODEL * DINNER / 4;
        split_pack_B<<<(n4 + 255) / 256, 256>>>(W_out, wouthi, woutlo, DMODEL, n4);
    }
    // 4) proj = x @ W_in^T   [16384, 2576]   <- profiled slot
    {
        dim3 grid(PROJPAD / 128, TOKENS / 256);
        gemm_tc<<<grid, 256, GEMM_SMEM_BYTES>>>(xhi, xlo, winhi, winlo,
                                                proj_ptr, DMODEL / 64, PROJ, PROJ);
    }
    // 5) intra-chunk (+dt)
    intra_kernel<<<BATCH * NCHUNK * NHEADS, 256>>>(dt_W, dt_b, A_log);
    // 6) chunk scan
    scan_kernel<<<BATCH * NHEADS * 4, 256>>>();
    // 7) cross-chunk + skip
    cross_kernel<<<BATCH * NCHUNK * NHEADS, 256>>>(D_par);
    // 8) RMS norm + gate -> packed bf16 hi/lo
    norm_kernel<<<TOKENS, 256>>>(norm_w);
    // 9) out = yg @ W_out^T  [16384, 1024]
    {
        dim3 grid(DMODEL / 128, TOKENS / 256);
        gemm_tc<<<grid, 256, GEMM_SMEM_BYTES>>>(yghi, yglo, wouthi, woutlo,
                                                out, DINNER / 64, DMODEL, DMODEL);
    }
}

// round 16
// speedup vs baseline: 1.1040x; 1.0229x over previous
#include <cuda_runtime.h>
#include <cuda_bf16.h>
#include <cstdint>

// ---------------------------------------------------------------------------
// Problem constants
// ---------------------------------------------------------------------------
#define BATCH   4
#define SEQ     4096
#define TOKENS  (BATCH * SEQ)        // 16384
#define DMODEL  1024
#define DINNER  1024
#define NHEADS  16
#define HDIM    64
#define DSTATE  16
#define DTRANK  16
#define CHUNK   64
#define NCHUNK  (SEQ / CHUNK)        // 64
#define PROJ    2576
#define PROJPAD 2688                 // 21 * 128

#define OFF_XP   0
#define OFF_Z    1024
#define OFF_B    2048
#define OFF_C    2304
#define OFF_DT   2560

// Packed-operand block offsets (bytes). A-pack: 256-row tiles; B-pack: 128-row.
// Both GEMMs have K=1024 -> exactly 16 chunks of 64 columns.
#define APK_BLK(mt, ch) ((((size_t)(mt) * 16) + (size_t)(ch)) * 32768)
#define BPK_BLK(nt, ch) ((((size_t)(nt) * 16) + (size_t)(ch)) * 16384)
#define SW128(o) ((o) ^ (((o) >> 3) & 0x70))

// tcgen05 is an arch-SPECIFIC feature: only emit it in the sm_103a/f passes.
#if defined(__CUDA_ARCH_FEAT_SM103_ALL) || \
    (defined(__CUDA_ARCH_FAMILY_SPECIFIC__) && __CUDA_ARCH_FAMILY_SPECIFIC__ >= 1000) || \
    (defined(__CUDA_ARCH_SPECIFIC__) && __CUDA_ARCH_SPECIFIC__ >= 1000)
#define HAS_TCGEN05 1
#else
#define HAS_TCGEN05 0
#endif

// ---------------------------------------------------------------------------
// PTX helpers (guarded)
// ---------------------------------------------------------------------------
#if HAS_TCGEN05
__device__ __forceinline__ uint32_t smem_to_u32(const void* p) {
    uint32_t a;
    asm("{ .reg .u64 t; cvta.to.shared.u64 t, %1; cvt.u32.u64 %0, t; }" : "=r"(a) : "l"(p));
    return a;
}
__device__ __forceinline__ uint32_t elect_one_pred() {
    uint32_t pred;
    asm volatile("{\n\t.reg .pred p;\n\telect.sync _|p, 0xFFFFFFFF;\n\tselp.b32 %0, 1, 0, p;\n\t}" : "=r"(pred));
    return pred;
}
#define TCGEN05_ALLOC(smem_result_addr, nCols) \
    asm volatile("tcgen05.alloc.cta_group::1.sync.aligned.shared::cta.b32 [%0], %1;" \
        :: "r"((uint32_t)(smem_result_addr)), "r"((uint32_t)(nCols)) : "memory")
#define TCGEN05_DEALLOC(tmem_addr, nCols) \
    asm volatile("tcgen05.dealloc.cta_group::1.sync.aligned.b32 %0, %1;" :: "r"(tmem_addr), "r"((uint32_t)(nCols)))
#define TCGEN05_RELINQUISH() \
    asm volatile("tcgen05.relinquish_alloc_permit.cta_group::1.sync.aligned;")
#define TCGEN05_COMMIT(mbar) \
    asm volatile("tcgen05.commit.cta_group::1.mbarrier::arrive::one.shared::cluster.b64 [%0];" \
        :: "r"((uint32_t)(mbar)) : "memory")
#define TCGEN05_FENCE_AFTER()  asm volatile("tcgen05.fence::after_thread_sync;" ::: "memory")
#define TCGEN05_FENCE_BEFORE() asm volatile("tcgen05.fence::before_thread_sync;" ::: "memory")
#define TCGEN05_WAIT_LD()      asm volatile("tcgen05.wait::ld.sync.aligned;" ::: "memory")
#define MBARRIER_INIT(mbar, count) \
    asm volatile("mbarrier.init.shared.b64 [%0], %1;" :: "r"((uint32_t)(mbar)), "r"((uint32_t)(count)) : "memory")
#define FENCE_PROXY_ASYNC() asm volatile("fence.proxy.async.shared::cta;" ::: "memory")
#define CP_ASYNC16(dst, src) \
    asm volatile("cp.async.cg.shared.global [%0], [%1], 16;" \
        :: "r"((uint32_t)(dst)), "l"(src) : "memory")
#define CP_ASYNC_COMMIT() asm volatile("cp.async.commit_group;" ::: "memory")
#define CP_ASYNC_WAIT0()  asm volatile("cp.async.wait_group 0;" ::: "memory")
#define CP_ASYNC_WAIT1()  asm volatile("cp.async.wait_group 1;" ::: "memory")
#define MBARRIER_WAIT_PARITY(mbar, parity) do { \
    uint32_t _m = (uint32_t)(mbar); uint32_t _p = (uint32_t)(parity); uint32_t _d; \
    asm volatile("{\n\t.reg .pred p;\n\t" \
        "mbarrier.try_wait.parity.acquire.cta.shared::cta.b64 p, [%1], %2;\n\t" \
        "selp.b32 %0, 1, 0, p;\n\t}" : "=r"(_d) : "r"(_m), "r"(_p) : "memory"); \
    if (!_d) { \
        asm volatile("{\n\t.reg .pred P1;\n\t" \
            "WL_%=:\n\t" \
            "mbarrier.try_wait.parity.acquire.cta.shared::cta.b64 P1, [%0], %1, 0x989680;\n\t" \
            "@P1 bra.uni WD_%=;\n\t" \
            "bra.uni WL_%=;\n\t" \
            "WD_%=:\n\t}" :: "r"(_m), "r"(_p) : "memory"); \
    } } while (0)
#define TCGEN05_LD_32X32B_X32(r, tmem_addr) \
    asm volatile("tcgen05.ld.sync.aligned.32x32b.x32.b32 " \
        "{%0, %1, %2, %3, %4, %5, %6, %7, %8, %9, %10, %11, %12, %13, %14, %15, " \
        " %16, %17, %18, %19, %20, %21, %22, %23, %24, %25, %26, %27, %28, %29, %30, %31}, [%32];" \
        : "=r"((r)[0]),  "=r"((r)[1]),  "=r"((r)[2]),  "=r"((r)[3]), \
          "=r"((r)[4]),  "=r"((r)[5]),  "=r"((r)[6]),  "=r"((r)[7]), \
          "=r"((r)[8]),  "=r"((r)[9]),  "=r"((r)[10]), "=r"((r)[11]), \
          "=r"((r)[12]), "=r"((r)[13]), "=r"((r)[14]), "=r"((r)[15]), \
          "=r"((r)[16]), "=r"((r)[17]), "=r"((r)[18]), "=r"((r)[19]), \
          "=r"((r)[20]), "=r"((r)[21]), "=r"((r)[22]), "=r"((r)[23]), \
          "=r"((r)[24]), "=r"((r)[25]), "=r"((r)[26]), "=r"((r)[27]), \
          "=r"((r)[28]), "=r"((r)[29]), "=r"((r)[30]), "=r"((r)[31]) \
        : "r"(tmem_addr))

static constexpr uint64_t SMEM_DESC_BASE_SW128 =
    (uint64_t(2) << 61) | (uint64_t(1) << 46) | (uint64_t(64) << 32) | (uint64_t(1) << 16);
#define MAKE_SMEM_DESC(base_addr) (SMEM_DESC_BASE_SW128 | ((uint64_t)((base_addr) >> 4) & 0x3FFF))

// idesc: dtype=F32(bit4), atype=BF16(bit7), btype=BF16(bit10), N/8 @17, M/16 @24
#define MMA_IDESC_128x128 ((1u << 4) | (1u << 7) | (1u << 10) | (16u << 17) | (8u << 24))

__device__ __forceinline__ void mma_f16_ss(uint32_t d_tmem, uint64_t a_desc, uint64_t b_desc,
                                           uint32_t idesc, uint32_t enable)
{
    asm volatile(
        "{\n\t.reg .pred p;\n\t"
        "setp.ne.u32 p, %4, 0;\n\t"
        "tcgen05.mma.cta_group::1.kind::f16 [%0], %1, %2, %3, {%5, %5, %5, %5}, p;\n\t"
        "}"
        :: "r"(d_tmem), "l"(a_desc), "l"(b_desc), "r"(idesc), "r"(enable), "r"(0u)
        : "memory");
}
#endif  // HAS_TCGEN05

// ---------------------------------------------------------------------------
// Scratch (device globals; no allocation allowed)
// ---------------------------------------------------------------------------
__device__ float g_proj[(size_t)TOKENS * PROJ];
__device__ float g_dacs[(size_t)TOKENS * NHEADS];
__device__ float g_y[(size_t)TOKENS * DINNER];
__device__ float g_cs[(size_t)BATCH * NCHUNK * NHEADS * DSTATE * HDIM];
__device__ float g_hs[(size_t)BATCH * NCHUNK * NHEADS * DSTATE * HDIM];
__device__ float g_cdecay[(size_t)BATCH * NCHUNK * NHEADS];

__device__ __align__(1024) uint8_t g_xhi[(size_t)TOKENS * DMODEL * 2];
__device__ __align__(1024) uint8_t g_xlo[(size_t)TOKENS * DMODEL * 2];
__device__ __align__(1024) uint8_t g_winhi[(size_t)PROJPAD * DMODEL * 2];
__device__ __align__(1024) uint8_t g_winlo[(size_t)PROJPAD * DMODEL * 2];
__device__ __align__(1024) uint8_t g_wouthi[(size_t)DMODEL * DINNER * 2];
__device__ __align__(1024) uint8_t g_woutlo[(size_t)DMODEL * DINNER * 2];
__device__ __align__(1024) uint8_t g_yghi[(size_t)TOKENS * DINNER * 2];
__device__ __align__(1024) uint8_t g_yglo[(size_t)TOKENS * DINNER * 2];

// ---------------------------------------------------------------------------
// hi/lo split helper
// ---------------------------------------------------------------------------
__device__ __forceinline__ void split4(float4 v, uint2& h, uint2& l)
{
    __nv_bfloat16 hx = __float2bfloat16(v.x), hy = __float2bfloat16(v.y);
    __nv_bfloat16 hz = __float2bfloat16(v.z), hw = __float2bfloat16(v.w);
    __nv_bfloat162 h01 = {hx, hy}, h23 = {hz, hw};
    __nv_bfloat162 l01 = {__float2bfloat16(v.x - __bfloat162float(hx)),
                          __float2bfloat16(v.y - __bfloat162float(hy))};
    __nv_bfloat162 l23 = {__float2bfloat16(v.z - __bfloat162float(hz)),
                          __float2bfloat16(v.w - __bfloat162float(hw))};
    h.x = *reinterpret_cast<uint32_t*>(&h01);
    h.y = *reinterpret_cast<uint32_t*>(&h23);
    l.x = *reinterpret_cast<uint32_t*>(&l01);
    l.y = *reinterpret_cast<uint32_t*>(&l23);
}

// Pack activations (256-row A tiles): src [rows][1024] fp32 -> swizzled blocks
__global__ void __launch_bounds__(256)
split_pack_A(const float* __restrict__ src, uint8_t* __restrict__ hi,
             uint8_t* __restrict__ lo, int n4)
{
    int i = blockIdx.x * 256 + threadIdx.x;
    if (i >= n4) return;
    int t  = i >> 8;
    int k0 = (i & 255) * 4;
    float4 v = reinterpret_cast<const float4*>(src)[i];
    uint2 h, l;
    split4(v, h, l);
    size_t  blk = APK_BLK(t >> 8, k0 >> 6);
    uint32_t off = (uint32_t)((t & 255) * 128 + (k0 & 63) * 2);
    off = SW128(off);
    *reinterpret_cast<uint2*>(hi + blk + off) = h;
    *reinterpret_cast<uint2*>(lo + blk + off) = l;
}

// Pack weights (128-row B tiles) with zero row padding
__global__ void __launch_bounds__(256)
split_pack_B(const float* __restrict__ src, uint8_t* __restrict__ hi,
             uint8_t* __restrict__ lo, int rows_src, int n4)
{
    int i = blockIdx.x * 256 + threadIdx.x;
    if (i >= n4) return;
    int r  = i >> 8;
    int k0 = (i & 255) * 4;
    float4 v = make_float4(0.f, 0.f, 0.f, 0.f);
    if (r < rows_src) v = reinterpret_cast<const float4*>(src)[i];
    uint2 h, l;
    split4(v, h, l);
    size_t  blk = BPK_BLK(r >> 7, k0 >> 6);
    uint32_t off = (uint32_t)((r & 127) * 128 + (k0 & 63) * 2);
    off = SW128(off);
    *reinterpret_cast<uint2*>(hi + blk + off) = h;
    *reinterpret_cast<uint2*>(lo + blk + off) = l;
}

// ---------------------------------------------------------------------------
// tcgen05 bf16-split GEMM, packed operands, cp.async staging.
// Single 96KB stage + 2 CTAs/SM (cross-CTA overlap) + intra-chunk hi-first:
// the hi copy-group (Ahi+Bhi) lands first, the 8 hi*hi MMAs execute while the
// lo group (Alo+Blo) streams; cross terms issue after lo arrives; one commit.
// Per-CTA loop: wait done(c-1) -> copy_hi(c), copy_lo(c) -> wait_group 1 ->
// sync -> hi*hi MMAs -> wait_group 0 -> sync -> cross MMAs -> commit.
// Every thread walks every done phase in order (one final drain for NC-1).
// Stage layout: Ahi @0 (32K), Alo @32768, Bhi @65536 (16K), Blo @81920.
// ---------------------------------------------------------------------------
#define STAGE_BYTES 98304
#define GEMM_SMEM_BYTES (2048 + STAGE_BYTES)

#if HAS_TCGEN05
__device__ __forceinline__ void gemm_copy_hi(
    uint32_t stage, int tid,
    const uint8_t* __restrict__ Ahi, const uint8_t* __restrict__ Bhi,
    int mt, int nt, int c)
{
    const uint8_t* sAh = Ahi + APK_BLK(mt, c);
    const uint8_t* sBh = Bhi + BPK_BLK(nt, c);
#pragma unroll
    for (int it = 0; it < 8; ++it) {
        uint32_t b = (uint32_t)(it * 256 + tid) * 16u;   // 0..32767
        CP_ASYNC16(stage + b, sAh + b);
    }
#pragma unroll
    for (int it = 0; it < 4; ++it) {
        uint32_t b = (uint32_t)(it * 256 + tid) * 16u;   // 0..16383
        CP_ASYNC16(stage + 65536u + b, sBh + b);
    }
    CP_ASYNC_COMMIT();
}
__device__ __forceinline__ void gemm_copy_lo(
    uint32_t stage, int tid,
    const uint8_t* __restrict__ Alo, const uint8_t* __restrict__ Blo,
    int mt, int nt, int c)
{
    const uint8_t* sAl = Alo + APK_BLK(mt, c);
    const uint8_t* sBl = Blo + BPK_BLK(nt, c);
#pragma unroll
    for (int it = 0; it < 8; ++it) {
        uint32_t b = (uint32_t)(it * 256 + tid) * 16u;
        CP_ASYNC16(stage + 32768u + b, sAl + b);
    }
#pragma unroll
    for (int it = 0; it < 4; ++it) {
        uint32_t b = (uint32_t)(it * 256 + tid) * 16u;
        CP_ASYNC16(stage + 81920u + b, sBl + b);
    }
    CP_ASYNC_COMMIT();
}
#endif

__global__ void __launch_bounds__(256, 2)
gemm_tc(const uint8_t* __restrict__ Ahi, const uint8_t* __restrict__ Alo,
        const uint8_t* __restrict__ Bhi, const uint8_t* __restrict__ Blo,
        float* __restrict__ C, int NC, int Nstride, int Nout)
{
#if HAS_TCGEN05
    extern __shared__ char smem[];
    const uint32_t sbase = smem_to_u32(smem);
    const int tid = threadIdx.x;
    const int wid = tid >> 5;
    const int lid = tid & 31;
    const int bm = blockIdx.y * 256;
    const int bn = blockIdx.x * 128;

    const uint32_t TMEMP = sbase;
    const uint32_t DONE0 = sbase + 8;
    const uint32_t DONE1 = sbase + 16;
    const uint32_t BUF   = (sbase + 32 + 1023) & ~1023u;

    if (wid == 0) {
        TCGEN05_ALLOC(TMEMP, 256);
        TCGEN05_RELINQUISH();
    }
    if (tid == 0) { MBARRIER_INIT(DONE0, 1); MBARRIER_INIT(DONE1, 1); }
    __syncthreads();
    uint32_t tmem;
    asm volatile("ld.shared.b32 %0, [%1];" : "=r"(tmem) : "r"(TMEMP));

    for (int c = 0; c < NC; ++c) {
        // stage reuse: MMA(c-1) must have finished reading it
        if (c >= 1) {
            const uint32_t pdone = ((c - 1) & 1) ? DONE1 : DONE0;
            MBARRIER_WAIT_PARITY(pdone, ((c - 1) >> 1) & 1);
        }
        gemm_copy_hi(BUF, tid, Ahi, Bhi, blockIdx.y, blockIdx.x, c);
        gemm_copy_lo(BUF, tid, Alo, Blo, blockIdx.y, blockIdx.x, c);

        CP_ASYNC_WAIT1();          // hi group landed; lo still streaming
        __syncthreads();
        if (wid == 0) {
            FENCE_PROXY_ASYNC();
            if (elect_one_pred()) {
                uint64_t dA0h = MAKE_SMEM_DESC(BUF);
                uint64_t dA1h = MAKE_SMEM_DESC(BUF + 16384);
                uint64_t dBh  = MAKE_SMEM_DESC(BUF + 65536);
#pragma unroll
                for (int ks = 0; ks < 4; ++ks) {
                    uint32_t en0 = (c == 0 && ks == 0) ? 0u : 1u;
                    mma_f16_ss(tmem,       dA0h + ks * 2, dBh + ks * 2, MMA_IDESC_128x128, en0);
                    mma_f16_ss(tmem + 128, dA1h + ks * 2, dBh + ks * 2, MMA_IDESC_128x128, en0);
                }
            }
        }

        CP_ASYNC_WAIT0();          // lo group landed
        __syncthreads();
        if (wid == 0) {
            FENCE_PROXY_ASYNC();
            if (elect_one_pred()) {
                uint64_t dA0h = MAKE_SMEM_DESC(BUF);
                uint64_t dA1h = MAKE_SMEM_DESC(BUF + 16384);
                uint64_t dA0l = MAKE_SMEM_DESC(BUF + 32768);
                uint64_t dA1l = MAKE_SMEM_DESC(BUF + 49152);
                uint64_t dBh  = MAKE_SMEM_DESC(BUF + 65536);
                uint64_t dBl  = MAKE_SMEM_DESC(BUF + 81920);
#pragma unroll
                for (int ks = 0; ks < 4; ++ks) {
                    mma_f16_ss(tmem,       dA0h + ks * 2, dBl + ks * 2, MMA_IDESC_128x128, 1u);
                    mma_f16_ss(tmem,       dA0l + ks * 2, dBh + ks * 2, MMA_IDESC_128x128, 1u);
                    mma_f16_ss(tmem + 128, dA1h + ks * 2, dBl + ks * 2, MMA_IDESC_128x128, 1u);
                    mma_f16_ss(tmem + 128, dA1l + ks * 2, dBh + ks * 2, MMA_IDESC_128x128, 1u);
                }
                TCGEN05_COMMIT(((c & 1) ? DONE1 : DONE0));
            }
        }
        __syncthreads();   // all threads see the commit before next iteration
    }

    // final drain: done(NC-1); done(NC-2) was walked in iteration NC-1
    MBARRIER_WAIT_PARITY(((NC - 1) & 1) ? DONE1 : DONE0, ((NC - 1) >> 1) & 1);
    TCGEN05_FENCE_AFTER();

    {
        int mt  = wid >> 2;                       // 0 or 1
        int row = bm + mt * 128 + (wid & 3) * 32 + lid;
        float* crow = C + (size_t)row * Nstride + bn;
        uint32_t tcol = tmem + (uint32_t)(mt * 128);
#pragma unroll
        for (int g = 0; g < 4; ++g) {
            uint32_t r[32];
            TCGEN05_LD_32X32B_X32(r, tcol + g * 32);
            TCGEN05_WAIT_LD();
            int n0 = bn + g * 32;
            if (n0 + 32 <= Nout) {
#pragma unroll
                for (int j = 0; j < 32; j += 4) {
                    float4 v = make_float4(__uint_as_float(r[j]), __uint_as_float(r[j + 1]),
                                           __uint_as_float(r[j + 2]), __uint_as_float(r[j + 3]));
                    *reinterpret_cast<float4*>(crow + g * 32 + j) = v;
                }
            } else {
                for (int j = 0; j < 32; ++j)
                    if (n0 + j < Nout) crow[g * 32 + j] = __uint_as_float(r[j]);
            }
        }
        TCGEN05_FENCE_BEFORE();
    }
    __syncthreads();
    if (wid == 0) TCGEN05_DEALLOC(tmem, 256);

#else   // ---------------- SIMT fallback (generic PTX pass only; never runs) --
    const int tid = threadIdx.x;
    const int bm  = blockIdx.y * 256;
    const int bn  = blockIdx.x * 128;
    const int K   = NC * 64;
    for (int e = tid; e < 256 * 128; e += 256) {
        int i = e >> 7, j = e & 127;
        int m = bm + i, n = bn + j;
        if (n >= Nout) continue;
        float acc = 0.f;
        for (int k = 0; k < K; ++k) {
            size_t ablk = APK_BLK(m >> 8, k >> 6);
            uint32_t aoff = SW128((uint32_t)((m & 255) * 128 + (k & 63) * 2));
            size_t bblk = BPK_BLK(n >> 7, k >> 6);
            uint32_t boff = SW128((uint32_t)((n & 127) * 128 + (k & 63) * 2));
            float a = __bfloat162float(*(const __nv_bfloat16*)(Ahi + ablk + aoff)) +
                      __bfloat162float(*(const __nv_bfloat16*)(Alo + ablk + aoff));
            float b = __bfloat162float(*(const __nv_bfloat16*)(Bhi + bblk + boff)) +
                      __bfloat162float(*(const __nv_bfloat16*)(Blo + bblk + boff));
            acc = fmaf(a, b, acc);
        }
        C[(size_t)m * Nstride + n] = acc;
    }
#endif
}

// ---------------------------------------------------------------------------
// Intra-chunk (dt folded in): dt -> dacs -> scores(T) -> y_intra, chunk_state
// ---------------------------------------------------------------------------
__global__ void __launch_bounds__(256, 3)
intra_kernel(const float* __restrict__ dt_W, const float* __restrict__ dt_b,
             const float* __restrict__ A_log)
{
    const int bid = blockIdx.x;        // (b*NCHUNK + c)*NHEADS + h
    const int h   = bid & 15;
    const int bc  = bid >> 4;
    const int t0  = bc * CHUNK;
    const int tid = threadIdx.x;
    const int wid = tid >> 5;
    const int lid = tid & 31;

    __shared__ float xs[64][68];
    __shared__ float scT[64][68];      // scT[k][i] = scores[i][k]
    __shared__ float Bsh[64][20];
    __shared__ float Csh[64][20];      // reused as bw after scores
    __shared__ float dts[64];
    __shared__ float dacs[64];
    __shared__ float wk[64];

    for (int idx = tid; idx < 64 * 16; idx += 256) {
        int k = idx >> 4, p4 = idx & 15;
        float4 v = *reinterpret_cast<const float4*>(
            g_proj + (size_t)(t0 + k) * PROJ + OFF_XP + h * HDIM + p4 * 4);
        *reinterpret_cast<float4*>(&xs[k][p4 * 4]) = v;
    }
    {
        int k = tid >> 2, n4 = tid & 3;
        float4 vb = *reinterpret_cast<const float4*>(
            g_proj + (size_t)(t0 + k) * PROJ + OFF_B + h * DSTATE + n4 * 4);
        float4 vc = *reinterpret_cast<const float4*>(
            g_proj + (size_t)(t0 + k) * PROJ + OFF_C + h * DSTATE + n4 * 4);
        *reinterpret_cast<float4*>(&Bsh[k][n4 * 4]) = vb;
        *reinterpret_cast<float4*>(&Csh[k][n4 * 4]) = vc;
    }
    if (tid < 64) {
        const float* row = g_proj + (size_t)(t0 + tid) * PROJ + OFF_DT;
        float acc = dt_b[h];
#pragma unroll
        for (int r = 0; r < DTRANK; ++r)
            acc = fmaf(row[r], dt_W[h * DTRANK + r], acc);
        dts[tid] = (acc > 20.f) ? acc : log1pf(expf(acc));
    }
    __syncthreads();

    if (wid == 0) {
        float A  = -expf(A_log[h]);
        float v1 = dts[2 * lid + 1] * A;
        float s  = dts[2 * lid] * A + v1;
#pragma unroll
        for (int off = 1; off < 32; off <<= 1) {
            float t = __shfl_up_sync(0xffffffffu, s, off);
            if (lid >= off) s += t;
        }
        dacs[2 * lid + 1] = s;
        dacs[2 * lid]     = s - v1;
    }
    __syncthreads();

    if (tid < 64) {
        wk[tid] = dts[tid] * expf(dacs[63] - dacs[tid]);
        g_dacs[(size_t)(t0 + tid) * NHEADS + h] = dacs[tid];
    }
    if (tid == 0) g_cdecay[bid] = expf(dacs[63]);
    __syncthreads();

    // scores: thread owns row i = tid&63, columns j0..j0+15; writes transposed.
    {
        int i  = tid & 63;
        int j0 = (tid >> 6) * 16;
        float ci[16];
#pragma unroll
        for (int n = 0; n < 16; ++n) ci[n] = Csh[i][n];
        float di = dacs[i];
#pragma unroll
        for (int jj = 0; jj < 16; ++jj) {
            int j = j0 + jj;
            float v = 0.f;
            if (j <= i) {
                float d = 0.f;
#pragma unroll
                for (int q = 0; q < 4; ++q) {
                    float4 b4 = *reinterpret_cast<const float4*>(&Bsh[j][q * 4]);
                    d = fmaf(ci[q * 4 + 0], b4.x, d);
                    d = fmaf(ci[q * 4 + 1], b4.y, d);
                    d = fmaf(ci[q * 4 + 2], b4.z, d);
                    d = fmaf(ci[q * 4 + 3], b4.w, d);
                }
                v = d * expf(di - dacs[j]) * dts[j];
            }
            scT[j][i] = v;
        }
    }
    __syncthreads();

    // bw[k][n] = B[k][n] * wk[k]  (overwrite Csh, dead after scores)
    for (int idx = tid; idx < 64 * 16; idx += 256) {
        int k = idx >> 4, n = idx & 15;
        Csh[k][n] = Bsh[k][n] * wk[k];
    }
    __syncthreads();

    // y_intra: 4x4 register blocking, causal-truncated k loop, float4 LDS both
    {
        int a  = tid >> 4;
        int b  = tid & 15;
        int i0 = a * 4, p0 = b * 4;
        float acc[4][4];
#pragma unroll
        for (int q = 0; q < 4; ++q)
#pragma unroll
            for (int r = 0; r < 4; ++r) acc[q][r] = 0.f;
        const int kmax = i0 + 4;          // scT[k][i] = 0 for k > i
        for (int kk = 0; kk < kmax; ++kk) {
            float4 s4 = *reinterpret_cast<const float4*>(&scT[kk][i0]);
            float4 xr = *reinterpret_cast<const float4*>(&xs[kk][p0]);
            acc[0][0] = fmaf(s4.x, xr.x, acc[0][0]);
            acc[0][1] = fmaf(s4.x, xr.y, acc[0][1]);
            acc[0][2] = fmaf(s4.x, xr.z, acc[0][2]);
            acc[0][3] = fmaf(s4.x, xr.w, acc[0][3]);
            acc[1][0] = fmaf(s4.y, xr.x, acc[1][0]);
            acc[1][1] = fmaf(s4.y, xr.y, acc[1][1]);
            acc[1][2] = fmaf(s4.y, xr.z, acc[1][2]);
            acc[1][3] = fmaf(s4.y, xr.w, acc[1][3]);
            acc[2][0] = fmaf(s4.z, xr.x, acc[2][0]);
            acc[2][1] = fmaf(s4.z, xr.y, acc[2][1]);
            acc[2][2] = fmaf(s4.z, xr.z, acc[2][2]);
            acc[2][3] = fmaf(s4.z, xr.w, acc[2][3]);
            acc[3][0] = fmaf(s4.w, xr.x, acc[3][0]);
            acc[3][1] = fmaf(s4.w, xr.y, acc[3][1]);
            acc[3][2] = fmaf(s4.w, xr.z, acc[3][2]);
            acc[3][3] = fmaf(s4.w, xr.w, acc[3][3]);
        }
#pragma unroll
        for (int q = 0; q < 4; ++q) {
            float4 v = make_float4(acc[q][0], acc[q][1], acc[q][2], acc[q][3]);
            *reinterpret_cast<float4*>(
                g_y + (size_t)(t0 + i0 + q) * DINNER + h * HDIM + p0) = v;
        }
    }

    // chunk_state[n][p] = sum_k bw[k][n] * x[k][p]
    {
        int n  = tid >> 4;
        int p0 = (tid & 15) * 4;
        float4 acc = make_float4(0.f, 0.f, 0.f, 0.f);
        for (int k = 0; k < 64; ++k) {
            float bwv = Csh[k][n];
            float4 xr = *reinterpret_cast<const float4*>(&xs[k][p0]);
            acc.x = fmaf(bwv, xr.x, acc.x);
            acc.y = fmaf(bwv, xr.y, acc.y);
            acc.z = fmaf(bwv, xr.z, acc.z);
            acc.w = fmaf(bwv, xr.w, acc.w);
        }
        *reinterpret_cast<float4*>(
            g_cs + (size_t)bid * (DSTATE * HDIM) + n * HDIM + p0) = acc;
    }
}

// ---------------------------------------------------------------------------
// Sequential scan over chunks: grid = BATCH*NHEADS*4, 1 elem/thread
// ---------------------------------------------------------------------------
__global__ void __launch_bounds__(256)
scan_kernel()
{
    const int g   = blockIdx.x;
    const int bh  = g >> 2;
    const int seg = g & 3;
    const int b   = bh >> 4;
    const int h   = bh & 15;
    const int e   = seg * 256 + threadIdx.x;

    const int    chid0  = (b * NCHUNK) * NHEADS + h;
    const size_t base   = (size_t)chid0 * (DSTATE * HDIM);
    const size_t stride = (size_t)NHEADS * DSTATE * HDIM;

    float hv  = 0.f;
    float cur = g_cs[base + e];
    float d   = g_cdecay[chid0];
    for (int c = 0; c < NCHUNK; ++c) {
        float nxt = 0.f, dn = 0.f;
        if (c + 1 < NCHUNK) {
            nxt = g_cs[base + stride * (c + 1) + e];
            dn  = g_cdecay[chid0 + (c + 1) * NHEADS];
        }
        g_hs[base + stride * c + e] = hv;
        hv = fmaf(d, hv, cur);
        cur = nxt; d = dn;
    }
}

// ---------------------------------------------------------------------------
// Cross-chunk + skip (hs rows loaded as float4)
// ---------------------------------------------------------------------------
__global__ void __launch_bounds__(256, 2)
cross_kernel(const float* __restrict__ D_param)
{
    const int bid = blockIdx.x;
    const int h   = bid & 15;
    const int bc  = bid >> 4;
    const int t0  = bc * CHUNK;
    const int tid = threadIdx.x;

    __shared__ float hs[16][68];
    __shared__ float Csh[64][20];
    __shared__ float dacs[64];

    {
        int n = tid >> 4, pg = tid & 15;
        float4 v = *reinterpret_cast<const float4*>(
            g_hs + (size_t)bid * (DSTATE * HDIM) + n * HDIM + pg * 4);
        *reinterpret_cast<float4*>(&hs[n][pg * 4]) = v;
    }
    {
        int k = tid >> 2, n4 = tid & 3;
        float4 vc = *reinterpret_cast<const float4*>(
            g_proj + (size_t)(t0 + k) * PROJ + OFF_C + h * DSTATE + n4 * 4);
        *reinterpret_cast<float4*>(&Csh[k][n4 * 4]) = vc;
    }
    if (tid < 64) dacs[tid] = g_dacs[(size_t)(t0 + tid) * NHEADS + h];
    __syncthreads();

    int i  = tid >> 2;
    int p0 = (tid & 3) * 16;
    float ci[16];
#pragma unroll
    for (int n = 0; n < 16; ++n) ci[n] = Csh[i][n];
    float e  = expf(dacs[i]);
    float dp = D_param[h];

    size_t t = (size_t)(t0 + i);
    const float* xrow = g_proj + t * PROJ + OFF_XP + h * HDIM;
    float* yrow = g_y + t * DINNER + h * HDIM;
#pragma unroll
    for (int g4 = 0; g4 < 4; ++g4) {
        int p = p0 + g4 * 4;
        float4 yv = *reinterpret_cast<const float4*>(yrow + p);
        float4 xv = *reinterpret_cast<const float4*>(xrow + p);
        float a0 = 0.f, a1 = 0.f, a2 = 0.f, a3 = 0.f;
#pragma unroll
        for (int n = 0; n < 16; ++n) {
            float c = ci[n];
            float4 h4 = *reinterpret_cast<const float4*>(&hs[n][p]);
            a0 = fmaf(c, h4.x, a0);
            a1 = fmaf(c, h4.y, a1);
            a2 = fmaf(c, h4.z, a2);
            a3 = fmaf(c, h4.w, a3);
        }
        float4 o;
        o.x = yv.x + e * a0 + dp * xv.x;
        o.y = yv.y + e * a1 + dp * xv.y;
        o.z = yv.z + e * a2 + dp * xv.z;
        o.w = yv.w + e * a3 + dp * xv.w;
        *reinterpret_cast<float4*>(yrow + p) = o;
    }
}

// ---------------------------------------------------------------------------
// RMS norm + SiLU gate -> yg packed (bf16 hi/lo, swizzled A-tile layout)
// ---------------------------------------------------------------------------
__global__ void __launch_bounds__(256)
norm_kernel(const float* __restrict__ norm_w)
{
    const int t   = blockIdx.x;
    const int tid = threadIdx.x;

    float4 v = reinterpret_cast<const float4*>(g_y + (size_t)t * DINNER)[tid];
    float ss = v.x * v.x + v.y * v.y + v.z * v.z + v.w * v.w;
#pragma unroll
    for (int off = 16; off > 0; off >>= 1)
        ss += __shfl_xor_sync(0xffffffffu, ss, off);

    __shared__ float red[8];
    __shared__ float s_inv;
    if ((tid & 31) == 0) red[tid >> 5] = ss;
    __syncthreads();
    if (tid == 0) {
        float s = 0.f;
#pragma unroll
        for (int i = 0; i < 8; ++i) s += red[i];
        s_inv = rsqrtf(s * (1.f / DINNER) + 1e-6f);
    }
    __syncthreads();
    float inv = s_inv;

    const float* zrow = g_proj + (size_t)t * PROJ + OFF_Z;
    int c = tid * 4;
    float4 z4 = *reinterpret_cast<const float4*>(zrow + c);
    float4 w4 = *reinterpret_cast<const float4*>(norm_w + c);
    float4 o;
    o.x = v.x * inv * w4.x * (z4.x / (1.f + expf(-z4.x)));
    o.y = v.y * inv * w4.y * (z4.y / (1.f + expf(-z4.y)));
    o.z = v.z * inv * w4.z * (z4.z / (1.f + expf(-z4.z)));
    o.w = v.w * inv * w4.w * (z4.w / (1.f + expf(-z4.w)));

    uint2 h, l;
    split4(o, h, l);
    size_t  blk = APK_BLK(t >> 8, c >> 6);
    uint32_t off = (uint32_t)((t & 255) * 128 + (c & 63) * 2);
    off = SW128(off);
    *reinterpret_cast<uint2*>(g_yghi + blk + off) = h;
    *reinterpret_cast<uint2*>(g_yglo + blk + off) = l;
}

// ---------------------------------------------------------------------------
// Launch — intra_kernel moved to slot #4 (profiled) to find the missing time
// ---------------------------------------------------------------------------
extern "C" void kernel_launch(void* const* d_in, const int* in_sizes, int n_in,
                              void* d_out, int out_size)
{
    const float* x      = (const float*)d_in[0];
    const float* W_in   = (const float*)d_in[1];
    const float* dt_W   = (const float*)d_in[2];
    const float* dt_b   = (const float*)d_in[3];
    const float* A_log  = (const float*)d_in[4];
    const float* D_par  = (const float*)d_in[5];
    const float* W_out  = (const float*)d_in[6];
    const float* norm_w = (const float*)d_in[7];
    float* out = (float*)d_out;

    float* proj_ptr = nullptr;
    uint8_t *xhi, *xlo, *winhi, *winlo, *wouthi, *woutlo, *yghi, *yglo;
    cudaGetSymbolAddress((void**)&proj_ptr, g_proj);
    cudaGetSymbolAddress((void**)&xhi, g_xhi);
    cudaGetSymbolAddress((void**)&xlo, g_xlo);
    cudaGetSymbolAddress((void**)&winhi, g_winhi);
    cudaGetSymbolAddress((void**)&winlo, g_winlo);
    cudaGetSymbolAddress((void**)&wouthi, g_wouthi);
    cudaGetSymbolAddress((void**)&woutlo, g_woutlo);
    cudaGetSymbolAddress((void**)&yghi, g_yghi);
    cudaGetSymbolAddress((void**)&yglo, g_yglo);

    cudaFuncSetAttribute(gemm_tc, cudaFuncAttributeMaxDynamicSharedMemorySize, GEMM_SMEM_BYTES);

    // 1) pack x
    {
        int n4 = TOKENS * DMODEL / 4;
        split_pack_A<<<(n4 + 255) / 256, 256>>>(x, xhi, xlo, n4);
    }
    // 2) pack W_in (padded to 2688 rows)
    {
        int n4 = PROJPAD * DMODEL / 4;
        split_pack_B<<<(n4 + 255) / 256, 256>>>(W_in, winhi, winlo, PROJ, n4);
    }
    // 3) proj = x @ W_in^T   [16384, 2576]
    {
        dim3 grid(PROJPAD / 128, TOKENS / 256);
        gemm_tc<<<grid, 256, GEMM_SMEM_BYTES>>>(xhi, xlo, winhi, winlo,
                                                proj_ptr, DMODEL / 64, PROJ, PROJ);
    }
    // 4) intra-chunk (+dt)   <- profiled slot
    intra_kernel<<<BATCH * NCHUNK * NHEADS, 256>>>(dt_W, dt_b, A_log);
    // 5) chunk scan
    scan_kernel<<<BATCH * NHEADS * 4, 256>>>();
    // 6) cross-chunk + skip
    cross_kernel<<<BATCH * NCHUNK * NHEADS, 256>>>(D_par);
    // 7) RMS norm + gate -> packed bf16 hi/lo
    norm_kernel<<<TOKENS, 256>>>(norm_w);
    // 8) pack W_out
    {
        int n4 = DMODEL * DINNER / 4;
        split_pack_B<<<(n4 + 255) / 256, 256>>>(W_out, wouthi, woutlo, DMODEL, n4);
    }
    // 9) out = yg @ W_out^T  [16384, 1024]
    {
        dim3 grid(DMODEL / 128, TOKENS / 256);
        gemm_tc<<<grid, 256, GEMM_SMEM_BYTES>>>(yghi, yglo, wouthi, woutlo,
                                                out, DINNER / 64, DMODEL, DMODEL);
    }
}

// round 17
// speedup vs baseline: 1.1094x; 1.0049x over previous
#include <cuda_runtime.h>
#include <cuda_bf16.h>
#include <cstdint>

// ---------------------------------------------------------------------------
// Problem constants
// ---------------------------------------------------------------------------
#define BATCH   4
#define SEQ     4096
#define TOKENS  (BATCH * SEQ)        // 16384
#define DMODEL  1024
#define DINNER  1024
#define NHEADS  16
#define HDIM    64
#define DSTATE  16
#define DTRANK  16
#define CHUNK   64
#define NCHUNK  (SEQ / CHUNK)        // 64
#define PROJ    2576
#define PROJPAD 2688                 // 21 * 128

#define OFF_XP   0
#define OFF_Z    1024
#define OFF_B    2048
#define OFF_C    2304
#define OFF_DT   2560

// Packed-operand block offsets (bytes). A-pack: 256-row tiles; B-pack: 128-row.
// Both GEMMs have K=1024 -> exactly 16 chunks of 64 columns.
#define APK_BLK(mt, ch) ((((size_t)(mt) * 16) + (size_t)(ch)) * 32768)
#define BPK_BLK(nt, ch) ((((size_t)(nt) * 16) + (size_t)(ch)) * 16384)
#define SW128(o) ((o) ^ (((o) >> 3) & 0x70))

// tcgen05 is an arch-SPECIFIC feature: only emit it in the sm_103a/f passes.
#if defined(__CUDA_ARCH_FEAT_SM103_ALL) || \
    (defined(__CUDA_ARCH_FAMILY_SPECIFIC__) && __CUDA_ARCH_FAMILY_SPECIFIC__ >= 1000) || \
    (defined(__CUDA_ARCH_SPECIFIC__) && __CUDA_ARCH_SPECIFIC__ >= 1000)
#define HAS_TCGEN05 1
#else
#define HAS_TCGEN05 0
#endif

// ---------------------------------------------------------------------------
// PTX helpers (guarded)
// ---------------------------------------------------------------------------
#if HAS_TCGEN05
__device__ __forceinline__ uint32_t smem_to_u32(const void* p) {
    uint32_t a;
    asm("{ .reg .u64 t; cvta.to.shared.u64 t, %1; cvt.u32.u64 %0, t; }" : "=r"(a) : "l"(p));
    return a;
}
__device__ __forceinline__ uint32_t elect_one_pred() {
    uint32_t pred;
    asm volatile("{\n\t.reg .pred p;\n\telect.sync _|p, 0xFFFFFFFF;\n\tselp.b32 %0, 1, 0, p;\n\t}" : "=r"(pred));
    return pred;
}
#define TCGEN05_ALLOC(smem_result_addr, nCols) \
    asm volatile("tcgen05.alloc.cta_group::1.sync.aligned.shared::cta.b32 [%0], %1;" \
        :: "r"((uint32_t)(smem_result_addr)), "r"((uint32_t)(nCols)) : "memory")
#define TCGEN05_DEALLOC(tmem_addr, nCols) \
    asm volatile("tcgen05.dealloc.cta_group::1.sync.aligned.b32 %0, %1;" :: "r"(tmem_addr), "r"((uint32_t)(nCols)))
#define TCGEN05_RELINQUISH() \
    asm volatile("tcgen05.relinquish_alloc_permit.cta_group::1.sync.aligned;")
#define TCGEN05_COMMIT(mbar) \
    asm volatile("tcgen05.commit.cta_group::1.mbarrier::arrive::one.shared::cluster.b64 [%0];" \
        :: "r"((uint32_t)(mbar)) : "memory")
#define TCGEN05_FENCE_AFTER()  asm volatile("tcgen05.fence::after_thread_sync;" ::: "memory")
#define TCGEN05_FENCE_BEFORE() asm volatile("tcgen05.fence::before_thread_sync;" ::: "memory")
#define TCGEN05_WAIT_LD()      asm volatile("tcgen05.wait::ld.sync.aligned;" ::: "memory")
#define MBARRIER_INIT(mbar, count) \
    asm volatile("mbarrier.init.shared.b64 [%0], %1;" :: "r"((uint32_t)(mbar)), "r"((uint32_t)(count)) : "memory")
#define FENCE_PROXY_ASYNC() asm volatile("fence.proxy.async.shared::cta;" ::: "memory")
#define CP_ASYNC16(dst, src) \
    asm volatile("cp.async.cg.shared.global [%0], [%1], 16;" \
        :: "r"((uint32_t)(dst)), "l"(src) : "memory")
#define CP_ASYNC_COMMIT() asm volatile("cp.async.commit_group;" ::: "memory")
#define CP_ASYNC_WAIT0()  asm volatile("cp.async.wait_group 0;" ::: "memory")
#define CP_ASYNC_WAIT1()  asm volatile("cp.async.wait_group 1;" ::: "memory")
#define MBARRIER_WAIT_PARITY(mbar, parity) do { \
    uint32_t _m = (uint32_t)(mbar); uint32_t _p = (uint32_t)(parity); uint32_t _d; \
    asm volatile("{\n\t.reg .pred p;\n\t" \
        "mbarrier.try_wait.parity.acquire.cta.shared::cta.b64 p, [%1], %2;\n\t" \
        "selp.b32 %0, 1, 0, p;\n\t}" : "=r"(_d) : "r"(_m), "r"(_p) : "memory"); \
    if (!_d) { \
        asm volatile("{\n\t.reg .pred P1;\n\t" \
            "WL_%=:\n\t" \
            "mbarrier.try_wait.parity.acquire.cta.shared::cta.b64 P1, [%0], %1, 0x989680;\n\t" \
            "@P1 bra.uni WD_%=;\n\t" \
            "bra.uni WL_%=;\n\t" \
            "WD_%=:\n\t}" :: "r"(_m), "r"(_p) : "memory"); \
    } } while (0)
#define TCGEN05_LD_32X32B_X32(r, tmem_addr) \
    asm volatile("tcgen05.ld.sync.aligned.32x32b.x32.b32 " \
        "{%0, %1, %2, %3, %4, %5, %6, %7, %8, %9, %10, %11, %12, %13, %14, %15, " \
        " %16, %17, %18, %19, %20, %21, %22, %23, %24, %25, %26, %27, %28, %29, %30, %31}, [%32];" \
        : "=r"((r)[0]),  "=r"((r)[1]),  "=r"((r)[2]),  "=r"((r)[3]), \
          "=r"((r)[4]),  "=r"((r)[5]),  "=r"((r)[6]),  "=r"((r)[7]), \
          "=r"((r)[8]),  "=r"((r)[9]),  "=r"((r)[10]), "=r"((r)[11]), \
          "=r"((r)[12]), "=r"((r)[13]), "=r"((r)[14]), "=r"((r)[15]), \
          "=r"((r)[16]), "=r"((r)[17]), "=r"((r)[18]), "=r"((r)[19]), \
          "=r"((r)[20]), "=r"((r)[21]), "=r"((r)[22]), "=r"((r)[23]), \
          "=r"((r)[24]), "=r"((r)[25]), "=r"((r)[26]), "=r"((r)[27]), \
          "=r"((r)[28]), "=r"((r)[29]), "=r"((r)[30]), "=r"((r)[31]) \
        : "r"(tmem_addr))

static constexpr uint64_t SMEM_DESC_BASE_SW128 =
    (uint64_t(2) << 61) | (uint64_t(1) << 46) | (uint64_t(64) << 32) | (uint64_t(1) << 16);
#define MAKE_SMEM_DESC(base_addr) (SMEM_DESC_BASE_SW128 | ((uint64_t)((base_addr) >> 4) & 0x3FFF))

// idesc: dtype=F32(bit4), atype=BF16(bit7), btype=BF16(bit10), N/8 @17, M/16 @24
#define MMA_IDESC_128x128 ((1u << 4) | (1u << 7) | (1u << 10) | (16u << 17) | (8u << 24))

__device__ __forceinline__ void mma_f16_ss(uint32_t d_tmem, uint64_t a_desc, uint64_t b_desc,
                                           uint32_t idesc, uint32_t enable)
{
    asm volatile(
        "{\n\t.reg .pred p;\n\t"
        "setp.ne.u32 p, %4, 0;\n\t"
        "tcgen05.mma.cta_group::1.kind::f16 [%0], %1, %2, %3, {%5, %5, %5, %5}, p;\n\t"
        "}"
        :: "r"(d_tmem), "l"(a_desc), "l"(b_desc), "r"(idesc), "r"(enable), "r"(0u)
        : "memory");
}
#endif  // HAS_TCGEN05

// ---------------------------------------------------------------------------
// Scratch (device globals; no allocation allowed)
// ---------------------------------------------------------------------------
__device__ float g_proj[(size_t)TOKENS * PROJ];
__device__ float g_dacs[(size_t)TOKENS * NHEADS];
__device__ float g_y[(size_t)TOKENS * DINNER];
__device__ float g_cs[(size_t)BATCH * NCHUNK * NHEADS * DSTATE * HDIM];
__device__ float g_hs[(size_t)BATCH * NCHUNK * NHEADS * DSTATE * HDIM];
__device__ float g_cdecay[(size_t)BATCH * NCHUNK * NHEADS];

__device__ __align__(1024) uint8_t g_xhi[(size_t)TOKENS * DMODEL * 2];
__device__ __align__(1024) uint8_t g_xlo[(size_t)TOKENS * DMODEL * 2];
__device__ __align__(1024) uint8_t g_winhi[(size_t)PROJPAD * DMODEL * 2];
__device__ __align__(1024) uint8_t g_winlo[(size_t)PROJPAD * DMODEL * 2];
__device__ __align__(1024) uint8_t g_wouthi[(size_t)DMODEL * DINNER * 2];
__device__ __align__(1024) uint8_t g_woutlo[(size_t)DMODEL * DINNER * 2];
__device__ __align__(1024) uint8_t g_yghi[(size_t)TOKENS * DINNER * 2];
__device__ __align__(1024) uint8_t g_yglo[(size_t)TOKENS * DINNER * 2];

// ---------------------------------------------------------------------------
// hi/lo split helper
// ---------------------------------------------------------------------------
__device__ __forceinline__ void split4(float4 v, uint2& h, uint2& l)
{
    __nv_bfloat16 hx = __float2bfloat16(v.x), hy = __float2bfloat16(v.y);
    __nv_bfloat16 hz = __float2bfloat16(v.z), hw = __float2bfloat16(v.w);
    __nv_bfloat162 h01 = {hx, hy}, h23 = {hz, hw};
    __nv_bfloat162 l01 = {__float2bfloat16(v.x - __bfloat162float(hx)),
                          __float2bfloat16(v.y - __bfloat162float(hy))};
    __nv_bfloat162 l23 = {__float2bfloat16(v.z - __bfloat162float(hz)),
                          __float2bfloat16(v.w - __bfloat162float(hw))};
    h.x = *reinterpret_cast<uint32_t*>(&h01);
    h.y = *reinterpret_cast<uint32_t*>(&h23);
    l.x = *reinterpret_cast<uint32_t*>(&l01);
    l.y = *reinterpret_cast<uint32_t*>(&l23);
}

// Pack activations (256-row A tiles): src [rows][1024] fp32 -> swizzled blocks
__global__ void __launch_bounds__(256)
split_pack_A(const float* __restrict__ src, uint8_t* __restrict__ hi,
             uint8_t* __restrict__ lo, int n4)
{
    int i = blockIdx.x * 256 + threadIdx.x;
    if (i >= n4) return;
    int t  = i >> 8;
    int k0 = (i & 255) * 4;
    float4 v = reinterpret_cast<const float4*>(src)[i];
    uint2 h, l;
    split4(v, h, l);
    size_t  blk = APK_BLK(t >> 8, k0 >> 6);
    uint32_t off = (uint32_t)((t & 255) * 128 + (k0 & 63) * 2);
    off = SW128(off);
    *reinterpret_cast<uint2*>(hi + blk + off) = h;
    *reinterpret_cast<uint2*>(lo + blk + off) = l;
}

// Pack weights (128-row B tiles) with zero row padding
__global__ void __launch_bounds__(256)
split_pack_B(const float* __restrict__ src, uint8_t* __restrict__ hi,
             uint8_t* __restrict__ lo, int rows_src, int n4)
{
    int i = blockIdx.x * 256 + threadIdx.x;
    if (i >= n4) return;
    int r  = i >> 8;
    int k0 = (i & 255) * 4;
    float4 v = make_float4(0.f, 0.f, 0.f, 0.f);
    if (r < rows_src) v = reinterpret_cast<const float4*>(src)[i];
    uint2 h, l;
    split4(v, h, l);
    size_t  blk = BPK_BLK(r >> 7, k0 >> 6);
    uint32_t off = (uint32_t)((r & 127) * 128 + (k0 & 63) * 2);
    off = SW128(off);
    *reinterpret_cast<uint2*>(hi + blk + off) = h;
    *reinterpret_cast<uint2*>(lo + blk + off) = l;
}

// ---------------------------------------------------------------------------
// tcgen05 bf16-split GEMM, packed operands, cp.async staging.
// Single 96KB stage + 2 CTAs/SM (cross-CTA overlap) + intra-chunk hi-first.
// Stage layout: Ahi @0 (32K), Alo @32768, Bhi @65536 (16K), Blo @81920.
// ---------------------------------------------------------------------------
#define STAGE_BYTES 98304
#define GEMM_SMEM_BYTES (2048 + STAGE_BYTES)

#if HAS_TCGEN05
__device__ __forceinline__ void gemm_copy_hi(
    uint32_t stage, int tid,
    const uint8_t* __restrict__ Ahi, const uint8_t* __restrict__ Bhi,
    int mt, int nt, int c)
{
    const uint8_t* sAh = Ahi + APK_BLK(mt, c);
    const uint8_t* sBh = Bhi + BPK_BLK(nt, c);
#pragma unroll
    for (int it = 0; it < 8; ++it) {
        uint32_t b = (uint32_t)(it * 256 + tid) * 16u;   // 0..32767
        CP_ASYNC16(stage + b, sAh + b);
    }
#pragma unroll
    for (int it = 0; it < 4; ++it) {
        uint32_t b = (uint32_t)(it * 256 + tid) * 16u;   // 0..16383
        CP_ASYNC16(stage + 65536u + b, sBh + b);
    }
    CP_ASYNC_COMMIT();
}
__device__ __forceinline__ void gemm_copy_lo(
    uint32_t stage, int tid,
    const uint8_t* __restrict__ Alo, const uint8_t* __restrict__ Blo,
    int mt, int nt, int c)
{
    const uint8_t* sAl = Alo + APK_BLK(mt, c);
    const uint8_t* sBl = Blo + BPK_BLK(nt, c);
#pragma unroll
    for (int it = 0; it < 8; ++it) {
        uint32_t b = (uint32_t)(it * 256 + tid) * 16u;
        CP_ASYNC16(stage + 32768u + b, sAl + b);
    }
#pragma unroll
    for (int it = 0; it < 4; ++it) {
        uint32_t b = (uint32_t)(it * 256 + tid) * 16u;
        CP_ASYNC16(stage + 81920u + b, sBl + b);
    }
    CP_ASYNC_COMMIT();
}
#endif

__global__ void __launch_bounds__(256, 2)
gemm_tc(const uint8_t* __restrict__ Ahi, const uint8_t* __restrict__ Alo,
        const uint8_t* __restrict__ Bhi, const uint8_t* __restrict__ Blo,
        float* __restrict__ C, int NC, int Nstride, int Nout)
{
#if HAS_TCGEN05
    extern __shared__ char smem[];
    const uint32_t sbase = smem_to_u32(smem);
    const int tid = threadIdx.x;
    const int wid = tid >> 5;
    const int lid = tid & 31;
    const int bm = blockIdx.y * 256;
    const int bn = blockIdx.x * 128;

    const uint32_t TMEMP = sbase;
    const uint32_t DONE0 = sbase + 8;
    const uint32_t DONE1 = sbase + 16;
    const uint32_t BUF   = (sbase + 32 + 1023) & ~1023u;

    if (wid == 0) {
        TCGEN05_ALLOC(TMEMP, 256);
        TCGEN05_RELINQUISH();
    }
    if (tid == 0) { MBARRIER_INIT(DONE0, 1); MBARRIER_INIT(DONE1, 1); }
    __syncthreads();
    uint32_t tmem;
    asm volatile("ld.shared.b32 %0, [%1];" : "=r"(tmem) : "r"(TMEMP));

    for (int c = 0; c < NC; ++c) {
        // stage reuse: MMA(c-1) must have finished reading it
        if (c >= 1) {
            const uint32_t pdone = ((c - 1) & 1) ? DONE1 : DONE0;
            MBARRIER_WAIT_PARITY(pdone, ((c - 1) >> 1) & 1);
        }
        gemm_copy_hi(BUF, tid, Ahi, Bhi, blockIdx.y, blockIdx.x, c);
        gemm_copy_lo(BUF, tid, Alo, Blo, blockIdx.y, blockIdx.x, c);

        CP_ASYNC_WAIT1();          // hi group landed; lo still streaming
        __syncthreads();
        if (wid == 0) {
            FENCE_PROXY_ASYNC();
            if (elect_one_pred()) {
                uint64_t dA0h = MAKE_SMEM_DESC(BUF);
                uint64_t dA1h = MAKE_SMEM_DESC(BUF + 16384);
                uint64_t dBh  = MAKE_SMEM_DESC(BUF + 65536);
#pragma unroll
                for (int ks = 0; ks < 4; ++ks) {
                    uint32_t en0 = (c == 0 && ks == 0) ? 0u : 1u;
                    mma_f16_ss(tmem,       dA0h + ks * 2, dBh + ks * 2, MMA_IDESC_128x128, en0);
                    mma_f16_ss(tmem + 128, dA1h + ks * 2, dBh + ks * 2, MMA_IDESC_128x128, en0);
                }
            }
        }

        CP_ASYNC_WAIT0();          // lo group landed
        __syncthreads();
        if (wid == 0) {
            FENCE_PROXY_ASYNC();
            if (elect_one_pred()) {
                uint64_t dA0h = MAKE_SMEM_DESC(BUF);
                uint64_t dA1h = MAKE_SMEM_DESC(BUF + 16384);
                uint64_t dA0l = MAKE_SMEM_DESC(BUF + 32768);
                uint64_t dA1l = MAKE_SMEM_DESC(BUF + 49152);
                uint64_t dBh  = MAKE_SMEM_DESC(BUF + 65536);
                uint64_t dBl  = MAKE_SMEM_DESC(BUF + 81920);
#pragma unroll
                for (int ks = 0; ks < 4; ++ks) {
                    mma_f16_ss(tmem,       dA0h + ks * 2, dBl + ks * 2, MMA_IDESC_128x128, 1u);
                    mma_f16_ss(tmem,       dA0l + ks * 2, dBh + ks * 2, MMA_IDESC_128x128, 1u);
                    mma_f16_ss(tmem + 128, dA1h + ks * 2, dBl + ks * 2, MMA_IDESC_128x128, 1u);
                    mma_f16_ss(tmem + 128, dA1l + ks * 2, dBh + ks * 2, MMA_IDESC_128x128, 1u);
                }
                TCGEN05_COMMIT(((c & 1) ? DONE1 : DONE0));
            }
        }
        __syncthreads();   // all threads see the commit before next iteration
    }

    // final drain: done(NC-1); done(NC-2) was walked in iteration NC-1
    MBARRIER_WAIT_PARITY(((NC - 1) & 1) ? DONE1 : DONE0, ((NC - 1) >> 1) & 1);
    TCGEN05_FENCE_AFTER();

    {
        int mt  = wid >> 2;                       // 0 or 1
        int row = bm + mt * 128 + (wid & 3) * 32 + lid;
        float* crow = C + (size_t)row * Nstride + bn;
        uint32_t tcol = tmem + (uint32_t)(mt * 128);
#pragma unroll
        for (int g = 0; g < 4; ++g) {
            uint32_t r[32];
            TCGEN05_LD_32X32B_X32(r, tcol + g * 32);
            TCGEN05_WAIT_LD();
            int n0 = bn + g * 32;
            if (n0 + 32 <= Nout) {
#pragma unroll
                for (int j = 0; j < 32; j += 4) {
                    float4 v = make_float4(__uint_as_float(r[j]), __uint_as_float(r[j + 1]),
                                           __uint_as_float(r[j + 2]), __uint_as_float(r[j + 3]));
                    *reinterpret_cast<float4*>(crow + g * 32 + j) = v;
                }
            } else {
                for (int j = 0; j < 32; ++j)
                    if (n0 + j < Nout) crow[g * 32 + j] = __uint_as_float(r[j]);
            }
        }
        TCGEN05_FENCE_BEFORE();
    }
    __syncthreads();
    if (wid == 0) TCGEN05_DEALLOC(tmem, 256);

#else   // ---------------- SIMT fallback (generic PTX pass only; never runs) --
    const int tid = threadIdx.x;
    const int bm  = blockIdx.y * 256;
    const int bn  = blockIdx.x * 128;
    const int K   = NC * 64;
    for (int e = tid; e < 256 * 128; e += 256) {
        int i = e >> 7, j = e & 127;
        int m = bm + i, n = bn + j;
        if (n >= Nout) continue;
        float acc = 0.f;
        for (int k = 0; k < K; ++k) {
            size_t ablk = APK_BLK(m >> 8, k >> 6);
            uint32_t aoff = SW128((uint32_t)((m & 255) * 128 + (k & 63) * 2));
            size_t bblk = BPK_BLK(n >> 7, k >> 6);
            uint32_t boff = SW128((uint32_t)((n & 127) * 128 + (k & 63) * 2));
            float a = __bfloat162float(*(const __nv_bfloat16*)(Ahi + ablk + aoff)) +
                      __bfloat162float(*(const __nv_bfloat16*)(Alo + ablk + aoff));
            float b = __bfloat162float(*(const __nv_bfloat16*)(Bhi + bblk + boff)) +
                      __bfloat162float(*(const __nv_bfloat16*)(Blo + bblk + boff));
            acc = fmaf(a, b, acc);
        }
        C[(size_t)m * Nstride + n] = acc;
    }
#endif
}

// ---------------------------------------------------------------------------
// Intra-chunk (dt folded in): dt -> dacs -> scores(T) -> y_intra, chunk_state
// All transcendentals via MUFU intrinsics (__expf / __logf).
// ---------------------------------------------------------------------------
__global__ void __launch_bounds__(256, 3)
intra_kernel(const float* __restrict__ dt_W, const float* __restrict__ dt_b,
             const float* __restrict__ A_log)
{
    const int bid = blockIdx.x;        // (b*NCHUNK + c)*NHEADS + h
    const int h   = bid & 15;
    const int bc  = bid >> 4;
    const int t0  = bc * CHUNK;
    const int tid = threadIdx.x;
    const int wid = tid >> 5;
    const int lid = tid & 31;

    __shared__ float xs[64][68];
    __shared__ float scT[64][68];      // scT[k][i] = scores[i][k]
    __shared__ float Bsh[64][20];
    __shared__ float Csh[64][20];      // reused as bw after scores
    __shared__ float dts[64];
    __shared__ float dacs[64];
    __shared__ float wk[64];

    for (int idx = tid; idx < 64 * 16; idx += 256) {
        int k = idx >> 4, p4 = idx & 15;
        float4 v = *reinterpret_cast<const float4*>(
            g_proj + (size_t)(t0 + k) * PROJ + OFF_XP + h * HDIM + p4 * 4);
        *reinterpret_cast<float4*>(&xs[k][p4 * 4]) = v;
    }
    {
        int k = tid >> 2, n4 = tid & 3;
        float4 vb = *reinterpret_cast<const float4*>(
            g_proj + (size_t)(t0 + k) * PROJ + OFF_B + h * DSTATE + n4 * 4);
        float4 vc = *reinterpret_cast<const float4*>(
            g_proj + (size_t)(t0 + k) * PROJ + OFF_C + h * DSTATE + n4 * 4);
        *reinterpret_cast<float4*>(&Bsh[k][n4 * 4]) = vb;
        *reinterpret_cast<float4*>(&Csh[k][n4 * 4]) = vc;
    }
    if (tid < 64) {
        const float* row = g_proj + (size_t)(t0 + tid) * PROJ + OFF_DT;
        float acc = dt_b[h];
#pragma unroll
        for (int r = 0; r < DTRANK; ++r)
            acc = fmaf(row[r], dt_W[h * DTRANK + r], acc);
        dts[tid] = (acc > 20.f) ? acc : __logf(1.f + __expf(acc));
    }
    __syncthreads();

    if (wid == 0) {
        float A  = -__expf(A_log[h]);
        float v1 = dts[2 * lid + 1] * A;
        float s  = dts[2 * lid] * A + v1;
#pragma unroll
        for (int off = 1; off < 32; off <<= 1) {
            float t = __shfl_up_sync(0xffffffffu, s, off);
            if (lid >= off) s += t;
        }
        dacs[2 * lid + 1] = s;
        dacs[2 * lid]     = s - v1;
    }
    __syncthreads();

    if (tid < 64) {
        wk[tid] = dts[tid] * __expf(dacs[63] - dacs[tid]);
        g_dacs[(size_t)(t0 + tid) * NHEADS + h] = dacs[tid];
    }
    if (tid == 0) g_cdecay[bid] = __expf(dacs[63]);
    __syncthreads();

    // scores: thread owns row i = tid&63, columns j0..j0+15; writes transposed.
    {
        int i  = tid & 63;
        int j0 = (tid >> 6) * 16;
        float ci[16];
#pragma unroll
        for (int n = 0; n < 16; ++n) ci[n] = Csh[i][n];
        float di = dacs[i];
#pragma unroll
        for (int jj = 0; jj < 16; ++jj) {
            int j = j0 + jj;
            float v = 0.f;
            if (j <= i) {
                float d = 0.f;
#pragma unroll
                for (int q = 0; q < 4; ++q) {
                    float4 b4 = *reinterpret_cast<const float4*>(&Bsh[j][q * 4]);
                    d = fmaf(ci[q * 4 + 0], b4.x, d);
                    d = fmaf(ci[q * 4 + 1], b4.y, d);
                    d = fmaf(ci[q * 4 + 2], b4.z, d);
                    d = fmaf(ci[q * 4 + 3], b4.w, d);
                }
                v = d * __expf(di - dacs[j]) * dts[j];
            }
            scT[j][i] = v;
        }
    }
    __syncthreads();

    // bw[k][n] = B[k][n] * wk[k]  (overwrite Csh, dead after scores)
    for (int idx = tid; idx < 64 * 16; idx += 256) {
        int k = idx >> 4, n = idx & 15;
        Csh[k][n] = Bsh[k][n] * wk[k];
    }
    __syncthreads();

    // y_intra: 4x4 register blocking, causal-truncated k loop, float4 LDS both
    {
        int a  = tid >> 4;
        int b  = tid & 15;
        int i0 = a * 4, p0 = b * 4;
        float acc[4][4];
#pragma unroll
        for (int q = 0; q < 4; ++q)
#pragma unroll
            for (int r = 0; r < 4; ++r) acc[q][r] = 0.f;
        const int kmax = i0 + 4;          // scT[k][i] = 0 for k > i
        for (int kk = 0; kk < kmax; ++kk) {
            float4 s4 = *reinterpret_cast<const float4*>(&scT[kk][i0]);
            float4 xr = *reinterpret_cast<const float4*>(&xs[kk][p0]);
            acc[0][0] = fmaf(s4.x, xr.x, acc[0][0]);
            acc[0][1] = fmaf(s4.x, xr.y, acc[0][1]);
            acc[0][2] = fmaf(s4.x, xr.z, acc[0][2]);
            acc[0][3] = fmaf(s4.x, xr.w, acc[0][3]);
            acc[1][0] = fmaf(s4.y, xr.x, acc[1][0]);
            acc[1][1] = fmaf(s4.y, xr.y, acc[1][1]);
            acc[1][2] = fmaf(s4.y, xr.z, acc[1][2]);
            acc[1][3] = fmaf(s4.y, xr.w, acc[1][3]);
            acc[2][0] = fmaf(s4.z, xr.x, acc[2][0]);
            acc[2][1] = fmaf(s4.z, xr.y, acc[2][1]);
            acc[2][2] = fmaf(s4.z, xr.z, acc[2][2]);
            acc[2][3] = fmaf(s4.z, xr.w, acc[2][3]);
            acc[3][0] = fmaf(s4.w, xr.x, acc[3][0]);
            acc[3][1] = fmaf(s4.w, xr.y, acc[3][1]);
            acc[3][2] = fmaf(s4.w, xr.z, acc[3][2]);
            acc[3][3] = fmaf(s4.w, xr.w, acc[3][3]);
        }
#pragma unroll
        for (int q = 0; q < 4; ++q) {
            float4 v = make_float4(acc[q][0], acc[q][1], acc[q][2], acc[q][3]);
            *reinterpret_cast<float4*>(
                g_y + (size_t)(t0 + i0 + q) * DINNER + h * HDIM + p0) = v;
        }
    }

    // chunk_state[n][p] = sum_k bw[k][n] * x[k][p]
    {
        int n  = tid >> 4;
        int p0 = (tid & 15) * 4;
        float4 acc = make_float4(0.f, 0.f, 0.f, 0.f);
        for (int k = 0; k < 64; ++k) {
            float bwv = Csh[k][n];
            float4 xr = *reinterpret_cast<const float4*>(&xs[k][p0]);
            acc.x = fmaf(bwv, xr.x, acc.x);
            acc.y = fmaf(bwv, xr.y, acc.y);
            acc.z = fmaf(bwv, xr.z, acc.z);
            acc.w = fmaf(bwv, xr.w, acc.w);
        }
        *reinterpret_cast<float4*>(
            g_cs + (size_t)bid * (DSTATE * HDIM) + n * HDIM + p0) = acc;
    }
}

// ---------------------------------------------------------------------------
// Sequential scan over chunks: grid = BATCH*NHEADS*4, 1 elem/thread
// ---------------------------------------------------------------------------
__global__ void __launch_bounds__(256)
scan_kernel()
{
    const int g   = blockIdx.x;
    const int bh  = g >> 2;
    const int seg = g & 3;
    const int b   = bh >> 4;
    const int h   = bh & 15;
    const int e   = seg * 256 + threadIdx.x;

    const int    chid0  = (b * NCHUNK) * NHEADS + h;
    const size_t base   = (size_t)chid0 * (DSTATE * HDIM);
    const size_t stride = (size_t)NHEADS * DSTATE * HDIM;

    float hv  = 0.f;
    float cur = g_cs[base + e];
    float d   = g_cdecay[chid0];
    for (int c = 0; c < NCHUNK; ++c) {
        float nxt = 0.f, dn = 0.f;
        if (c + 1 < NCHUNK) {
            nxt = g_cs[base + stride * (c + 1) + e];
            dn  = g_cdecay[chid0 + (c + 1) * NHEADS];
        }
        g_hs[base + stride * c + e] = hv;
        hv = fmaf(d, hv, cur);
        cur = nxt; d = dn;
    }
}

// ---------------------------------------------------------------------------
// Cross-chunk + skip (hs rows loaded as float4); fast exp
// ---------------------------------------------------------------------------
__global__ void __launch_bounds__(256, 2)
cross_kernel(const float* __restrict__ D_param)
{
    const int bid = blockIdx.x;
    const int h   = bid & 15;
    const int bc  = bid >> 4;
    const int t0  = bc * CHUNK;
    const int tid = threadIdx.x;

    __shared__ float hs[16][68];
    __shared__ float Csh[64][20];
    __shared__ float dacs[64];

    {
        int n = tid >> 4, pg = tid & 15;
        float4 v = *reinterpret_cast<const float4*>(
            g_hs + (size_t)bid * (DSTATE * HDIM) + n * HDIM + pg * 4);
        *reinterpret_cast<float4*>(&hs[n][pg * 4]) = v;
    }
    {
        int k = tid >> 2, n4 = tid & 3;
        float4 vc = *reinterpret_cast<const float4*>(
            g_proj + (size_t)(t0 + k) * PROJ + OFF_C + h * DSTATE + n4 * 4);
        *reinterpret_cast<float4*>(&Csh[k][n4 * 4]) = vc;
    }
    if (tid < 64) dacs[tid] = g_dacs[(size_t)(t0 + tid) * NHEADS + h];
    __syncthreads();

    int i  = tid >> 2;
    int p0 = (tid & 3) * 16;
    float ci[16];
#pragma unroll
    for (int n = 0; n < 16; ++n) ci[n] = Csh[i][n];
    float e  = __expf(dacs[i]);
    float dp = D_param[h];

    size_t t = (size_t)(t0 + i);
    const float* xrow = g_proj + t * PROJ + OFF_XP + h * HDIM;
    float* yrow = g_y + t * DINNER + h * HDIM;
#pragma unroll
    for (int g4 = 0; g4 < 4; ++g4) {
        int p = p0 + g4 * 4;
        float4 yv = *reinterpret_cast<const float4*>(yrow + p);
        float4 xv = *reinterpret_cast<const float4*>(xrow + p);
        float a0 = 0.f, a1 = 0.f, a2 = 0.f, a3 = 0.f;
#pragma unroll
        for (int n = 0; n < 16; ++n) {
            float c = ci[n];
            float4 h4 = *reinterpret_cast<const float4*>(&hs[n][p]);
            a0 = fmaf(c, h4.x, a0);
            a1 = fmaf(c, h4.y, a1);
            a2 = fmaf(c, h4.z, a2);
            a3 = fmaf(c, h4.w, a3);
        }
        float4 o;
        o.x = yv.x + e * a0 + dp * xv.x;
        o.y = yv.y + e * a1 + dp * xv.y;
        o.z = yv.z + e * a2 + dp * xv.z;
        o.w = yv.w + e * a3 + dp * xv.w;
        *reinterpret_cast<float4*>(yrow + p) = o;
    }
}

// ---------------------------------------------------------------------------
// RMS norm + SiLU gate -> yg packed (bf16 hi/lo, swizzled A-tile layout)
// SiLU via __expf (MUFU).
// ---------------------------------------------------------------------------
__global__ void __launch_bounds__(256)
norm_kernel(const float* __restrict__ norm_w)
{
    const int t   = blockIdx.x;
    const int tid = threadIdx.x;

    float4 v = reinterpret_cast<const float4*>(g_y + (size_t)t * DINNER)[tid];
    float ss = v.x * v.x + v.y * v.y + v.z * v.z + v.w * v.w;
#pragma unroll
    for (int off = 16; off > 0; off >>= 1)
        ss += __shfl_xor_sync(0xffffffffu, ss, off);

    __shared__ float red[8];
    __shared__ float s_inv;
    if ((tid & 31) == 0) red[tid >> 5] = ss;
    __syncthreads();
    if (tid == 0) {
        float s = 0.f;
#pragma unroll
        for (int i = 0; i < 8; ++i) s += red[i];
        s_inv = rsqrtf(s * (1.f / DINNER) + 1e-6f);
    }
    __syncthreads();
    float inv = s_inv;

    const float* zrow = g_proj + (size_t)t * PROJ + OFF_Z;
    int c = tid * 4;
    float4 z4 = *reinterpret_cast<const float4*>(zrow + c);
    float4 w4 = *reinterpret_cast<const float4*>(norm_w + c);
    float4 o;
    o.x = v.x * inv * w4.x * (z4.x / (1.f + __expf(-z4.x)));
    o.y = v.y * inv * w4.y * (z4.y / (1.f + __expf(-z4.y)));
    o.z = v.z * inv * w4.z * (z4.z / (1.f + __expf(-z4.z)));
    o.w = v.w * inv * w4.w * (z4.w / (1.f + __expf(-z4.w)));

    uint2 h, l;
    split4(o, h, l);
    size_t  blk = APK_BLK(t >> 8, c >> 6);
    uint32_t off = (uint32_t)((t & 255) * 128 + (c & 63) * 2);
    off = SW128(off);
    *reinterpret_cast<uint2*>(g_yghi + blk + off) = h;
    *reinterpret_cast<uint2*>(g_yglo + blk + off) = l;
}

// ---------------------------------------------------------------------------
// Launch — intra_kernel at slot #4 (profiled; verifies the __expf prediction)
// ---------------------------------------------------------------------------
extern "C" void kernel_launch(void* const* d_in, const int* in_sizes, int n_in,
                              void* d_out, int out_size)
{
    const float* x      = (const float*)d_in[0];
    const float* W_in   = (const float*)d_in[1];
    const float* dt_W   = (const float*)d_in[2];
    const float* dt_b   = (const float*)d_in[3];
    const float* A_log  = (const float*)d_in[4];
    const float* D_par  = (const float*)d_in[5];
    const float* W_out  = (const float*)d_in[6];
    const float* norm_w = (const float*)d_in[7];
    float* out = (float*)d_out;

    float* proj_ptr = nullptr;
    uint8_t *xhi, *xlo, *winhi, *winlo, *wouthi, *woutlo, *yghi, *yglo;
    cudaGetSymbolAddress((void**)&proj_ptr, g_proj);
    cudaGetSymbolAddress((void**)&xhi, g_xhi);
    cudaGetSymbolAddress((void**)&xlo, g_xlo);
    cudaGetSymbolAddress((void**)&winhi, g_winhi);
    cudaGetSymbolAddress((void**)&winlo, g_winlo);
    cudaGetSymbolAddress((void**)&wouthi, g_wouthi);
    cudaGetSymbolAddress((void**)&woutlo, g_woutlo);
    cudaGetSymbolAddress((void**)&yghi, g_yghi);
    cudaGetSymbolAddress((void**)&yglo, g_yglo);

    cudaFuncSetAttribute(gemm_tc, cudaFuncAttributeMaxDynamicSharedMemorySize, GEMM_SMEM_BYTES);

    // 1) pack x
    {
        int n4 = TOKENS * DMODEL / 4;
        split_pack_A<<<(n4 + 255) / 256, 256>>>(x, xhi, xlo, n4);
    }
    // 2) pack W_in (padded to 2688 rows)
    {
        int n4 = PROJPAD * DMODEL / 4;
        split_pack_B<<<(n4 + 255) / 256, 256>>>(W_in, winhi, winlo, PROJ, n4);
    }
    // 3) proj = x @ W_in^T   [16384, 2576]
    {
        dim3 grid(PROJPAD / 128, TOKENS / 256);
        gemm_tc<<<grid, 256, GEMM_SMEM_BYTES>>>(xhi, xlo, winhi, winlo,
                                                proj_ptr, DMODEL / 64, PROJ, PROJ);
    }
    // 4) intra-chunk (+dt)   <- profiled slot
    intra_kernel<<<BATCH * NCHUNK * NHEADS, 256>>>(dt_W, dt_b, A_log);
    // 5) chunk scan
    scan_kernel<<<BATCH * NHEADS * 4, 256>>>();
    // 6) cross-chunk + skip
    cross_kernel<<<BATCH * NCHUNK * NHEADS, 256>>>(D_par);
    // 7) RMS norm + gate -> packed bf16 hi/lo
    norm_kernel<<<TOKENS, 256>>>(norm_w);
    // 8) pack W_out
    {
        int n4 = DMODEL * DINNER / 4;
        split_pack_B<<<(n4 + 255) / 256, 256>>>(W_out, wouthi, woutlo, DMODEL, n4);
    }
    // 9) out = yg @ W_out^T  [16384, 1024]
    {
        dim3 grid(DMODEL / 128, TOKENS / 256);
        gemm_tc<<<grid, 256, GEMM_SMEM_BYTES>>>(yghi, yglo, wouthi, woutlo,
                                                out, DINNER / 64, DMODEL, DMODEL);
    }
}